// round 8
// baseline (speedup 1.0000x reference)
#include <cuda_runtime.h>
#include <cuda_bf16.h>
#include <cstdint>

// ---------------- problem constants ----------------
#define Bv 8
#define Qv 1024
#define Sv 2048
#define Dm 1024
#define Hv 16
#define DH 64
#define MT 128            // q rows per CTA
#define ST 64             // s per tile
#define NTILES (Sv / ST)  // 32
#define NTH 256

// bf16 tile pitch (elements / bytes)
#define PB  72
#define PBB (PB * 2)      // 144 B per row

// ---------------- smem layout (bytes) ----------------
#define SM_QHI   0
#define SM_QLO   (SM_QHI + MT * PBB)      // 18432
#define SM_KHI   (SM_QLO + MT * PBB)      // 36864
#define SM_KLO   (SM_KHI + ST * PBB)      // 46080
#define SM_VHI   (SM_KLO + ST * PBB)      // 55296
#define SM_VLO   (SM_VHI + ST * PBB)      // 64512
#define SM_MASK  (SM_VLO + ST * PBB)      // 73728  (2048 u8)
#define SM_STAGE (SM_MASK + 2048)         // 75776
#define STP 68                            // stage pitch (floats)
#define SMEM_TOTAL (SM_STAGE + MT * STP * 4)   // 110592

// ---------------- helpers ----------------
__device__ __forceinline__ uint32_t su32(const void* p) {
    uint32_t a;
    asm("{ .reg .u64 t; cvta.to.shared.u64 t, %1; cvt.u32.u64 %0, t; }" : "=r"(a) : "l"(p));
    return a;
}

__device__ __forceinline__ void ldm4(uint32_t* r, uint32_t a) {
    asm volatile("ldmatrix.sync.aligned.m8n8.x4.shared.b16 {%0,%1,%2,%3}, [%4];"
        : "=r"(r[0]), "=r"(r[1]), "=r"(r[2]), "=r"(r[3]) : "r"(a));
}
__device__ __forceinline__ void ldm4t(uint32_t* r, uint32_t a) {
    asm volatile("ldmatrix.sync.aligned.m8n8.x4.trans.shared.b16 {%0,%1,%2,%3}, [%4];"
        : "=r"(r[0]), "=r"(r[1]), "=r"(r[2]), "=r"(r[3]) : "r"(a));
}
__device__ __forceinline__ void mma16816(float* d, const uint32_t* a, uint32_t b0, uint32_t b1) {
    asm volatile("mma.sync.aligned.m16n8k16.row.col.f32.bf16.bf16.f32 "
        "{%0,%1,%2,%3}, {%4,%5,%6,%7}, {%8,%9}, {%0,%1,%2,%3};"
        : "+f"(d[0]), "+f"(d[1]), "+f"(d[2]), "+f"(d[3])
        : "r"(a[0]), "r"(a[1]), "r"(a[2]), "r"(a[3]), "r"(b0), "r"(b1));
}

// pack two fp32 into bf16x2 hi + bf16x2 lo (split)
__device__ __forceinline__ void pack2(float e0, float e1, uint32_t& hi, uint32_t& lo) {
    __nv_bfloat162 h = __floats2bfloat162_rn(e0, e1);
    hi = *(uint32_t*)&h;
    float f0 = __bfloat162float(__low2bfloat16(h));
    float f1 = __bfloat162float(__high2bfloat16(h));
    __nv_bfloat162 l = __floats2bfloat162_rn(e0 - f0, e1 - f1);
    lo = *(uint32_t*)&l;
}

// split a float2 into hi/lo bf16x2 tiles at (row, dpair)
__device__ __forceinline__ void split_store(char* hib, char* lob, int row, int dp, float2 v) {
    uint32_t h, l;
    pack2(v.x, v.y, h, l);
    *(uint32_t*)(hib + row * PBB + dp * 4) = h;
    *(uint32_t*)(lob + row * PBB + dp * 4) = l;
}

// ======================= K1: fused attention (single kernel) =======================
extern __shared__ char smem[];

__global__ void __launch_bounds__(NTH, 2)
attn_k1(const float* __restrict__ Qg, const float* __restrict__ Kg,
        const float* __restrict__ Vg, const int* __restrict__ Mg,
        float* __restrict__ outg, float* __restrict__ attng)
{
    const int tid  = threadIdx.x;
    const int lane = tid & 31;
    const int wq   = tid >> 5;          // warp -> q rows [wq*16, wq*16+16)
    const int q0   = blockIdx.x * MT;
    const int h    = blockIdx.y;
    const int b    = blockIdx.z;

    const uint32_t sb = su32(smem);
    unsigned char* mk = (unsigned char*)(smem + SM_MASK);
    float* stg = (float*)(smem + SM_STAGE);

    // Q scale folds 1/sqrt(Dh)=0.125 and log2(e): exp(s) == exp2(s_scaled)
    const float QSCALE = 0.125f * 1.44269504088896f;

    // ---- prologue: Q (scaled, hi/lo split) + mask ----
    #pragma unroll 4
    for (int it = 0; it < 16; it++) {
        int idx = tid + it * NTH;
        int m = idx >> 5, dp = idx & 31;
        float2 v = *(const float2*)(Qg + ((size_t)(b * Qv + q0 + m)) * Dm + h * DH + dp * 2);
        v.x *= QSCALE; v.y *= QSCALE;
        split_store(smem + SM_QHI, smem + SM_QLO, m, dp, v);
    }
    for (int s = tid; s < Sv; s += NTH)
        mk[s] = (unsigned char)Mg[(size_t)b * Sv + s];

    const float* Kp = Kg + (size_t)b * Sv * Dm + h * DH;
    const float* Vp = Vg + (size_t)b * Sv * Dm + h * DH;

    // ---- per-thread ldmatrix addresses ----
    const uint32_t aAoff = (uint32_t)((wq * 16 + (lane & 15)) * PBB + ((lane & 16) >> 4) * 16);
    const uint32_t aAhi = sb + SM_QHI + aAoff;
    const uint32_t aAlo = sb + SM_QLO + aAoff;
    const uint32_t aBoff = (uint32_t)(((lane & 7) + ((lane & 16) >> 1)) * PBB + ((lane & 8) << 1));
    const uint32_t aVoff = (uint32_t)(((lane & 7) + (lane & 8)) * PBB + ((lane >> 4) & 1) * 16);

    const int r = lane >> 2, c = lane & 3;

    float O[8][4];
    #pragma unroll
    for (int nt = 0; nt < 8; nt++)
        #pragma unroll
        for (int j = 0; j < 4; j++) O[nt][j] = 0.0f;
    float rsl = 0.0f, rsh = 0.0f;

    for (int i = 0; i < NTILES; i++) {
        __syncthreads();     // previous iter's MMA2 done reading V
        // ---- load K(i), V(i) hi/lo (R4 structure: no register prefetch) ----
        #pragma unroll 4
        for (int it = 0; it < 8; it++) {
            int idx = tid + it * NTH;
            int rr = idx >> 5, dp = idx & 31;
            float2 kv = *(const float2*)(Kp + (size_t)(i * ST + rr) * Dm + dp * 2);
            split_store(smem + SM_KHI, smem + SM_KLO, rr, dp, kv);
            float2 vv = *(const float2*)(Vp + (size_t)(i * ST + rr) * Dm + dp * 2);
            split_store(smem + SM_VHI, smem + SM_VLO, rr, dp, vv);
        }
        __syncthreads();

        // ---- MMA1: S = Qs @ K^T (hi*hi + hi*lo + lo*hi) ----
        float S[8][4];
        #pragma unroll
        for (int nt = 0; nt < 8; nt++)
            #pragma unroll
            for (int j = 0; j < 4; j++) S[nt][j] = 0.0f;

        #pragma unroll
        for (int k4 = 0; k4 < 4; k4++) {
            uint32_t ah[4], al[4];
            ldm4(ah, aAhi + k4 * 32);
            ldm4(al, aAlo + k4 * 32);
            #pragma unroll
            for (int np = 0; np < 4; np++) {
                uint32_t bo = aBoff + np * 16 * PBB + k4 * 32;
                uint32_t bh[4], bl[4];
                ldm4(bh, sb + SM_KHI + bo);
                ldm4(bl, sb + SM_KLO + bo);
                mma16816(S[2*np],   ah, bh[0], bh[1]);
                mma16816(S[2*np+1], ah, bh[2], bh[3]);
                mma16816(S[2*np],   ah, bl[0], bl[1]);
                mma16816(S[2*np+1], ah, bl[2], bl[3]);
                mma16816(S[2*np],   al, bh[0], bh[1]);
                mma16816(S[2*np+1], al, bh[2], bh[3]);
            }
        }

        // ---- mask * exp2, rowsum, stage (unnormalized) ----
        const int s0 = i * ST;
        #pragma unroll
        for (int nt = 0; nt < 8; nt++) {
            int col = nt * 8 + 2 * c;
            float m0 = (float)mk[s0 + col], m1 = (float)mk[s0 + col + 1];
            float e0 = m0 * exp2f(S[nt][0]);
            float e1 = m1 * exp2f(S[nt][1]);
            float e2 = m0 * exp2f(S[nt][2]);
            float e3 = m1 * exp2f(S[nt][3]);
            rsl += e0 + e1; rsh += e2 + e3;
            S[nt][0] = e0; S[nt][1] = e1; S[nt][2] = e2; S[nt][3] = e3;
            *(float2*)&stg[(wq * 16 + r)     * STP + col] = make_float2(e0, e1);
            *(float2*)&stg[(wq * 16 + r + 8) * STP + col] = make_float2(e2, e3);
        }

        // ---- MMA2: O += P @ V (Phi*Vhi + Phi*Vlo + Plo*Vhi), P from registers ----
        #pragma unroll
        for (int kt = 0; kt < 4; kt++) {
            uint32_t ph[4], pl[4];
            pack2(S[2*kt][0],   S[2*kt][1],   ph[0], pl[0]);
            pack2(S[2*kt][2],   S[2*kt][3],   ph[1], pl[1]);
            pack2(S[2*kt+1][0], S[2*kt+1][1], ph[2], pl[2]);
            pack2(S[2*kt+1][2], S[2*kt+1][3], ph[3], pl[3]);
            #pragma unroll
            for (int np = 0; np < 4; np++) {
                uint32_t bo = aVoff + kt * 16 * PBB + np * 32;
                uint32_t vh4[4], vl4[4];
                ldm4t(vh4, sb + SM_VHI + bo);
                ldm4t(vl4, sb + SM_VLO + bo);
                mma16816(O[2*np],   ph, vh4[0], vh4[1]);
                mma16816(O[2*np+1], ph, vh4[2], vh4[3]);
                mma16816(O[2*np],   ph, vl4[0], vl4[1]);
                mma16816(O[2*np+1], ph, vl4[2], vl4[3]);
                mma16816(O[2*np],   pl, vh4[0], vh4[1]);
                mma16816(O[2*np+1], pl, vh4[2], vh4[3]);
            }
        }

        // ---- coalesced attention write (unnormalized e); drains during next loads ----
        __syncwarp();
        #pragma unroll
        for (int it = 0; it < 8; it++) {
            int row2 = it * 2 + (lane >> 4);       // 0..15
            int c4   = lane & 15;                  // float4 col
            float4 v = *(float4*)&stg[(wq * 16 + row2) * STP + c4 * 4];
            *(float4*)(attng + (((size_t)(b * Qv + q0 + wq * 16 + row2)) * Hv + h) * Sv
                       + s0 + c4 * 4) = v;
        }
    }

    // ---- rowsum reduce, rinv, normalize O, write out ----
    rsl += __shfl_xor_sync(0xffffffffu, rsl, 1);
    rsl += __shfl_xor_sync(0xffffffffu, rsl, 2);
    rsh += __shfl_xor_sync(0xffffffffu, rsh, 1);
    rsh += __shfl_xor_sync(0xffffffffu, rsh, 2);
    const float il = 1.0f / (rsl + 1e-13f);
    const float ih = 1.0f / (rsh + 1e-13f);

    __syncthreads();   // all tiles' stage traffic done before reusing stg

    // publish rinv per q-row into stage area
    if (c == 0) {
        stg[wq * 16 + r]     = il;
        stg[wq * 16 + r + 8] = ih;
    }

    float* orow0 = outg + (size_t)(b * Qv + q0 + wq * 16 + r)     * Dm + h * DH;
    float* orow1 = outg + (size_t)(b * Qv + q0 + wq * 16 + r + 8) * Dm + h * DH;
    #pragma unroll
    for (int nt = 0; nt < 8; nt++) {
        int col = nt * 8 + 2 * c;
        *(float2*)(orow0 + col) = make_float2(O[nt][0] * il, O[nt][1] * il);
        *(float2*)(orow1 + col) = make_float2(O[nt][2] * ih, O[nt][3] * ih);
    }

    __syncthreads();   // rinv table visible

    // ---- fused rescale tail: normalize this CTA's attn block in place ----
    // 128 rows x 512 float4 = 65536 float4, 256 per thread, coalesced.
    #pragma unroll 4
    for (int it = 0; it < (MT * (Sv / 4)) / NTH; it++) {
        int idx = tid + it * NTH;
        int row = idx >> 9;
        int col = idx & 511;
        float ri = stg[row];
        float4* p = (float4*)(attng + (((size_t)(b * Qv + q0 + row)) * Hv + h) * Sv) + col;
        float4 v = *p;
        v.x *= ri; v.y *= ri; v.z *= ri; v.w *= ri;
        *p = v;
    }
}

// ======================= launch =======================
extern "C" void kernel_launch(void* const* d_in, const int* in_sizes, int n_in,
                              void* d_out, int out_size)
{
    const float* Qg = (const float*)d_in[0];
    const float* Kg = (const float*)d_in[1];
    const float* Vg = (const float*)d_in[2];
    const int*   Mg = (const int*)d_in[3];

    float* outg  = (float*)d_out;                     // [B,Q,D]
    float* attng = outg + (size_t)Bv * Qv * Dm;       // [B,Q,H,S]

    cudaFuncSetAttribute(attn_k1, cudaFuncAttributeMaxDynamicSharedMemorySize, SMEM_TOTAL);

    dim3 grid(Qv / MT, Hv, Bv);                       // (8,16,8) = 1024 CTAs
    attn_k1<<<grid, NTH, SMEM_TOTAL>>>(Qg, Kg, Vg, Mg, outg, attng);
}

// round 9
// speedup vs baseline: 1.3478x; 1.3478x over previous
#include <cuda_runtime.h>
#include <cuda_bf16.h>
#include <cstdint>

// ---------------- problem constants ----------------
#define Bv 8
#define Qv 1024
#define Sv 2048
#define Dm 1024
#define Hv 16
#define DH 64
#define MT 128            // q rows per CTA
#define ST 64             // s per tile
#define NTILES (Sv / ST)  // 32
#define NTH 256

// bf16 tile pitch (elements / bytes)
#define PB  72
#define PBB (PB * 2)      // 144 B per row

// ---------------- smem layout (bytes) ----------------
#define SM_QHI   0
#define SM_QLO   (SM_QHI + MT * PBB)      // 18432
#define SM_KHI   (SM_QLO + MT * PBB)      // 36864  (K hi, K lo, V hi, V lo: 4 x 9216)
#define SM_KLO   (SM_KHI + ST * PBB)      // 46080
#define SM_VHI   (SM_KLO + ST * PBB)      // 55296
#define SM_VLO   (SM_VHI + ST * PBB)      // 64512
#define SM_MASK  (SM_VLO + ST * PBB)      // 73728  (2048 u8)
#define SM_RAW   (SM_MASK + 2048)         // 75776  raw fp32 KV staging (K 16K, V 16K)
#define SMEM_TOTAL (SM_RAW + 32768)       // 108544 -> 2 CTAs/SM

// ---------------- helpers ----------------
__device__ float g_rinv[Bv * Qv * Hv];

__device__ __forceinline__ uint32_t su32(const void* p) {
    uint32_t a;
    asm("{ .reg .u64 t; cvta.to.shared.u64 t, %1; cvt.u32.u64 %0, t; }" : "=r"(a) : "l"(p));
    return a;
}

__device__ __forceinline__ void cp_async16(uint32_t dst, const void* src) {
    asm volatile("cp.async.cg.shared.global [%0], [%1], 16;" :: "r"(dst), "l"(src));
}
#define CP_COMMIT() asm volatile("cp.async.commit_group;" ::: "memory")
#define CP_WAIT0()  asm volatile("cp.async.wait_group 0;" ::: "memory")

__device__ __forceinline__ void ldm4(uint32_t* r, uint32_t a) {
    asm volatile("ldmatrix.sync.aligned.m8n8.x4.shared.b16 {%0,%1,%2,%3}, [%4];"
        : "=r"(r[0]), "=r"(r[1]), "=r"(r[2]), "=r"(r[3]) : "r"(a));
}
__device__ __forceinline__ void ldm4t(uint32_t* r, uint32_t a) {
    asm volatile("ldmatrix.sync.aligned.m8n8.x4.trans.shared.b16 {%0,%1,%2,%3}, [%4];"
        : "=r"(r[0]), "=r"(r[1]), "=r"(r[2]), "=r"(r[3]) : "r"(a));
}
__device__ __forceinline__ void mma16816(float* d, const uint32_t* a, uint32_t b0, uint32_t b1) {
    asm volatile("mma.sync.aligned.m16n8k16.row.col.f32.bf16.bf16.f32 "
        "{%0,%1,%2,%3}, {%4,%5,%6,%7}, {%8,%9}, {%0,%1,%2,%3};"
        : "+f"(d[0]), "+f"(d[1]), "+f"(d[2]), "+f"(d[3])
        : "r"(a[0]), "r"(a[1]), "r"(a[2]), "r"(a[3]), "r"(b0), "r"(b1));
}

// pack two fp32 into bf16x2 hi + bf16x2 lo (split)
__device__ __forceinline__ void pack2(float e0, float e1, uint32_t& hi, uint32_t& lo) {
    __nv_bfloat162 h = __floats2bfloat162_rn(e0, e1);
    hi = *(uint32_t*)&h;
    float f0 = __bfloat162float(__low2bfloat16(h));
    float f1 = __bfloat162float(__high2bfloat16(h));
    __nv_bfloat162 l = __floats2bfloat162_rn(e0 - f0, e1 - f1);
    lo = *(uint32_t*)&l;
}

// split a float2 into hi/lo bf16x2 tiles at (row, dpair)
__device__ __forceinline__ void split_store(char* hib, char* lob, int row, int dp, float2 v) {
    uint32_t h, l;
    pack2(v.x, v.y, h, l);
    *(uint32_t*)(hib + row * PBB + dp * 4) = h;
    *(uint32_t*)(lob + row * PBB + dp * 4) = l;
}

// ======================= K1: fused attention =======================
extern __shared__ char smem[];

__global__ void __launch_bounds__(NTH, 2)
attn_k1(const float* __restrict__ Qg, const float* __restrict__ Kg,
        const float* __restrict__ Vg, const int* __restrict__ Mg,
        float* __restrict__ outg, float* __restrict__ attng)
{
    const int tid  = threadIdx.x;
    const int lane = tid & 31;
    const int wq   = tid >> 5;          // warp -> q rows [wq*16, wq*16+16)
    const int q0   = blockIdx.x * MT;
    const int h    = blockIdx.y;
    const int b    = blockIdx.z;

    const uint32_t sb = su32(smem);
    unsigned char* mk = (unsigned char*)(smem + SM_MASK);

    const float* Kp = Kg + (size_t)b * Sv * Dm + h * DH;
    const float* Vp = Vg + (size_t)b * Sv * Dm + h * DH;

    // per-thread cp.async / convert chunk mapping (identical for both phases)
    // idx = tid + it*NTH over 2048 chunks of 16B: [K 1024 | V 1024], 16 chunks/row
    // prime tile 0 FIRST so it flies during the Q/mask prologue loads
    #pragma unroll
    for (int it = 0; it < 8; it++) {
        int idx   = tid + it * NTH;
        int half  = idx >> 10;
        int row   = (idx >> 4) & 63;
        int col16 = idx & 15;
        const float* g = (half ? Vp : Kp) + (size_t)row * Dm + col16 * 4;
        cp_async16(sb + SM_RAW + half * 16384 + row * 256 + col16 * 16, g);
    }
    CP_COMMIT();

    // Q scale folds 1/sqrt(Dh)=0.125 and log2(e): exp(s) == exp2(s_scaled)
    const float QSCALE = 0.125f * 1.44269504088896f;

    // ---- prologue: Q (scaled, hi/lo split) + mask ----
    #pragma unroll 4
    for (int it = 0; it < 16; it++) {
        int idx = tid + it * NTH;
        int m = idx >> 5, dp = idx & 31;
        float2 v = *(const float2*)(Qg + ((size_t)(b * Qv + q0 + m)) * Dm + h * DH + dp * 2);
        v.x *= QSCALE; v.y *= QSCALE;
        split_store(smem + SM_QHI, smem + SM_QLO, m, dp, v);
    }
    for (int s = tid; s < Sv; s += NTH)
        mk[s] = (unsigned char)Mg[(size_t)b * Sv + s];

    // ---- per-thread ldmatrix addresses (layout identical to R4, verified) ----
    const uint32_t aAoff = (uint32_t)((wq * 16 + (lane & 15)) * PBB + ((lane & 16) >> 4) * 16);
    const uint32_t aAhi = sb + SM_QHI + aAoff;
    const uint32_t aAlo = sb + SM_QLO + aAoff;
    const uint32_t aBoff = (uint32_t)(((lane & 7) + ((lane & 16) >> 1)) * PBB + ((lane & 8) << 1));
    const uint32_t aVoff = (uint32_t)(((lane & 7) + (lane & 8)) * PBB + ((lane >> 4) & 1) * 16);

    const int r = lane >> 2, c = lane & 3;

    float O[8][4];
    #pragma unroll
    for (int nt = 0; nt < 8; nt++)
        #pragma unroll
        for (int j = 0; j < 4; j++) O[nt][j] = 0.0f;
    float rsl = 0.0f, rsh = 0.0f;

    // attn row bases for direct fragment writes
    float* arow0 = attng + (((size_t)(b * Qv + q0 + wq * 16 + r)) * Hv + h) * Sv;
    float* arow1 = attng + (((size_t)(b * Qv + q0 + wq * 16 + r + 8)) * Hv + h) * Sv;

    for (int i = 0; i < NTILES; i++) {
        // raw buffer holds tile i
        CP_WAIT0();
        __syncthreads();   // raw visible to all; also: all warps done with split V (MMA2 of i-1)

        // ---- convert raw fp32 -> split bf16 hi/lo tiles ----
        #pragma unroll
        for (int it = 0; it < 8; it++) {
            int idx   = tid + it * NTH;
            int half  = idx >> 10;
            int row   = (idx >> 4) & 63;
            int col16 = idx & 15;
            float4 f = *(float4*)(smem + SM_RAW + half * 16384 + row * 256 + col16 * 16);
            uint32_t h0, l0, h1, l1;
            pack2(f.x, f.y, h0, l0);
            pack2(f.z, f.w, h1, l1);
            char* hib = smem + SM_KHI + half * (2 * ST * PBB);
            char* lob = hib + ST * PBB;
            int off = row * PBB + col16 * 8;         // d0 = col16*4 -> byte d0*2
            *(uint2*)(hib + off) = make_uint2(h0, h1);
            *(uint2*)(lob + off) = make_uint2(l0, l1);
        }

        // ---- prefetch tile i+1 into raw (each thread overwrites only its own chunks) ----
        if (i + 1 < NTILES) {
            #pragma unroll
            for (int it = 0; it < 8; it++) {
                int idx   = tid + it * NTH;
                int half  = idx >> 10;
                int row   = (idx >> 4) & 63;
                int col16 = idx & 15;
                const float* g = (half ? Vp : Kp)
                               + (size_t)((i + 1) * ST + row) * Dm + col16 * 4;
                cp_async16(sb + SM_RAW + half * 16384 + row * 256 + col16 * 16, g);
            }
        }
        CP_COMMIT();
        __syncthreads();   // split tiles ready for ldmatrix

        // ---- MMA1: S = Qs @ K^T (hi*hi + hi*lo + lo*hi) ----
        float S[8][4];
        #pragma unroll
        for (int nt = 0; nt < 8; nt++)
            #pragma unroll
            for (int j = 0; j < 4; j++) S[nt][j] = 0.0f;

        #pragma unroll
        for (int k4 = 0; k4 < 4; k4++) {
            uint32_t ah[4], al[4];
            ldm4(ah, aAhi + k4 * 32);
            ldm4(al, aAlo + k4 * 32);
            #pragma unroll
            for (int np = 0; np < 4; np++) {
                uint32_t bo = aBoff + np * 16 * PBB + k4 * 32;
                uint32_t bh[4], bl[4];
                ldm4(bh, sb + SM_KHI + bo);
                ldm4(bl, sb + SM_KLO + bo);
                mma16816(S[2*np],   ah, bh[0], bh[1]);
                mma16816(S[2*np+1], ah, bh[2], bh[3]);
                mma16816(S[2*np],   ah, bl[0], bl[1]);
                mma16816(S[2*np+1], ah, bl[2], bl[3]);
                mma16816(S[2*np],   al, bh[0], bh[1]);
                mma16816(S[2*np+1], al, bh[2], bh[3]);
            }
        }

        // ---- mask * exp2, rowsum, direct coalesced attn write (32B sectors) ----
        const int s0 = i * ST;
        #pragma unroll
        for (int nt = 0; nt < 8; nt++) {
            int col = nt * 8 + 2 * c;
            float m0 = (float)mk[s0 + col], m1 = (float)mk[s0 + col + 1];
            float e0 = m0 * exp2f(S[nt][0]);
            float e1 = m1 * exp2f(S[nt][1]);
            float e2 = m0 * exp2f(S[nt][2]);
            float e3 = m1 * exp2f(S[nt][3]);
            rsl += e0 + e1; rsh += e2 + e3;
            S[nt][0] = e0; S[nt][1] = e1; S[nt][2] = e2; S[nt][3] = e3;
            *(float2*)(arow0 + s0 + col) = make_float2(e0, e1);
            *(float2*)(arow1 + s0 + col) = make_float2(e2, e3);
        }

        // ---- MMA2: O += P @ V (Phi*Vhi + Phi*Vlo + Plo*Vhi), P from registers ----
        #pragma unroll
        for (int kt = 0; kt < 4; kt++) {
            uint32_t ph[4], pl[4];
            pack2(S[2*kt][0],   S[2*kt][1],   ph[0], pl[0]);
            pack2(S[2*kt][2],   S[2*kt][3],   ph[1], pl[1]);
            pack2(S[2*kt+1][0], S[2*kt+1][1], ph[2], pl[2]);
            pack2(S[2*kt+1][2], S[2*kt+1][3], ph[3], pl[3]);
            #pragma unroll
            for (int np = 0; np < 4; np++) {
                uint32_t bo = aVoff + kt * 16 * PBB + np * 32;
                uint32_t vh4[4], vl4[4];
                ldm4t(vh4, sb + SM_VHI + bo);
                ldm4t(vl4, sb + SM_VLO + bo);
                mma16816(O[2*np],   ph, vh4[0], vh4[1]);
                mma16816(O[2*np+1], ph, vh4[2], vh4[3]);
                mma16816(O[2*np],   ph, vl4[0], vl4[1]);
                mma16816(O[2*np+1], ph, vl4[2], vl4[3]);
                mma16816(O[2*np],   pl, vh4[0], vh4[1]);
                mma16816(O[2*np+1], pl, vh4[2], vh4[3]);
            }
        }
    }

    // ---- rowsum reduce, rinv, normalize O, write out ----
    rsl += __shfl_xor_sync(0xffffffffu, rsl, 1);
    rsl += __shfl_xor_sync(0xffffffffu, rsl, 2);
    rsh += __shfl_xor_sync(0xffffffffu, rsh, 1);
    rsh += __shfl_xor_sync(0xffffffffu, rsh, 2);
    const float il = 1.0f / (rsl + 1e-13f);
    const float ih = 1.0f / (rsh + 1e-13f);

    if (c == 0) {
        g_rinv[(size_t)(b * Qv + q0 + wq * 16 + r)     * Hv + h] = il;
        g_rinv[(size_t)(b * Qv + q0 + wq * 16 + r + 8) * Hv + h] = ih;
    }

    float* orow0 = outg + (size_t)(b * Qv + q0 + wq * 16 + r)     * Dm + h * DH;
    float* orow1 = outg + (size_t)(b * Qv + q0 + wq * 16 + r + 8) * Dm + h * DH;
    #pragma unroll
    for (int nt = 0; nt < 8; nt++) {
        int col = nt * 8 + 2 * c;
        *(float2*)(orow0 + col) = make_float2(O[nt][0] * il, O[nt][1] * il);
        *(float2*)(orow1 + col) = make_float2(O[nt][2] * ih, O[nt][3] * ih);
    }
}

// ======================= K3: rescale attention (near DRAM roofline) =======================
__global__ void __launch_bounds__(256)
rescale_k3(float* __restrict__ attn)
{
    size_t i4 = (size_t)blockIdx.x * 256 + threadIdx.x;   // float4 index
    float rinv = g_rinv[i4 >> 9];                         // 512 float4 per (b,q,h) row
    float4* p = (float4*)attn + i4;
    float4 v = *p;
    v.x *= rinv; v.y *= rinv; v.z *= rinv; v.w *= rinv;
    *p = v;
}

// ======================= launch =======================
extern "C" void kernel_launch(void* const* d_in, const int* in_sizes, int n_in,
                              void* d_out, int out_size)
{
    const float* Qg = (const float*)d_in[0];
    const float* Kg = (const float*)d_in[1];
    const float* Vg = (const float*)d_in[2];
    const int*   Mg = (const int*)d_in[3];

    float* outg  = (float*)d_out;                     // [B,Q,D]
    float* attng = outg + (size_t)Bv * Qv * Dm;       // [B,Q,H,S]

    cudaFuncSetAttribute(attn_k1, cudaFuncAttributeMaxDynamicSharedMemorySize, SMEM_TOTAL);

    dim3 grid(Qv / MT, Hv, Bv);                       // (8,16,8) = 1024 CTAs
    attn_k1<<<grid, NTH, SMEM_TOTAL>>>(Qg, Kg, Vg, Mg, outg, attng);

    size_t n4 = (size_t)Bv * Qv * Hv * Sv / 4;        // 67,108,864 float4
    rescale_k3<<<(unsigned)(n4 / 256), 256>>>(attng);
}

// round 10
// speedup vs baseline: 1.3809x; 1.0245x over previous
#include <cuda_runtime.h>
#include <cuda_bf16.h>
#include <cstdint>

// ---------------- problem constants ----------------
#define Bv 8
#define Qv 1024
#define Sv 2048
#define Dm 1024
#define Hv 16
#define DH 64
#define MT 128            // q rows per CTA
#define ST 64             // s per tile
#define NTILES (Sv / ST)  // 32
#define NTH 256

// Q tile pitch (bf16 bytes) -- unchanged, proven conflict-free for A ldmatrix
#define PB  72
#define PBB (PB * 2)      // 144 B per row

// ---------------- smem layout (bytes) ----------------
#define SM_QHI   0
#define SM_QLO   (SM_QHI + MT * PBB)      // 18432
#define SM_MASK  (SM_QLO + MT * PBB)      // 36864 (2048 u8)
#define SM_KV    (SM_MASK + 2048)         // 38912: 2 bufs x 32768
#define SMEM_TOTAL (SM_KV + 2 * 32768)    // 104448 -> 2 CTAs/SM

// scratch: [b][h][tile][Khi|Klo|Vhi|Vlo][64 rows][128 B], XOR-swizzled chunks
__device__ __align__(16) unsigned char g_kv[(size_t)Bv * Hv * NTILES * 4 * ST * 128]; // 128 MB
__device__ float g_rinv[Bv * Qv * Hv];

// ---------------- helpers ----------------
__device__ __forceinline__ uint32_t su32(const void* p) {
    uint32_t a;
    asm("{ .reg .u64 t; cvta.to.shared.u64 t, %1; cvt.u32.u64 %0, t; }" : "=r"(a) : "l"(p));
    return a;
}

__device__ __forceinline__ void cp_async16(uint32_t dst, const void* src) {
    asm volatile("cp.async.cg.shared.global [%0], [%1], 16;" :: "r"(dst), "l"(src));
}
#define CP_COMMIT() asm volatile("cp.async.commit_group;" ::: "memory")
#define CP_WAIT0()  asm volatile("cp.async.wait_group 0;" ::: "memory")

__device__ __forceinline__ void ldm4(uint32_t* r, uint32_t a) {
    asm volatile("ldmatrix.sync.aligned.m8n8.x4.shared.b16 {%0,%1,%2,%3}, [%4];"
        : "=r"(r[0]), "=r"(r[1]), "=r"(r[2]), "=r"(r[3]) : "r"(a));
}
__device__ __forceinline__ void ldm4t(uint32_t* r, uint32_t a) {
    asm volatile("ldmatrix.sync.aligned.m8n8.x4.trans.shared.b16 {%0,%1,%2,%3}, [%4];"
        : "=r"(r[0]), "=r"(r[1]), "=r"(r[2]), "=r"(r[3]) : "r"(a));
}
__device__ __forceinline__ void mma16816(float* d, const uint32_t* a, uint32_t b0, uint32_t b1) {
    asm volatile("mma.sync.aligned.m16n8k16.row.col.f32.bf16.bf16.f32 "
        "{%0,%1,%2,%3}, {%4,%5,%6,%7}, {%8,%9}, {%0,%1,%2,%3};"
        : "+f"(d[0]), "+f"(d[1]), "+f"(d[2]), "+f"(d[3])
        : "r"(a[0]), "r"(a[1]), "r"(a[2]), "r"(a[3]), "r"(b0), "r"(b1));
}

// pack two fp32 into bf16x2 hi + bf16x2 lo (split)
__device__ __forceinline__ void pack2(float e0, float e1, uint32_t& hi, uint32_t& lo) {
    __nv_bfloat162 h = __floats2bfloat162_rn(e0, e1);
    hi = *(uint32_t*)&h;
    float f0 = __bfloat162float(__low2bfloat16(h));
    float f1 = __bfloat162float(__high2bfloat16(h));
    __nv_bfloat162 l = __floats2bfloat162_rn(e0 - f0, e1 - f1);
    lo = *(uint32_t*)&l;
}

// split a float2 into hi/lo bf16x2 tiles at (row, dpair) -- Q prologue only
__device__ __forceinline__ void split_store(char* hib, char* lob, int row, int dp, float2 v) {
    uint32_t h, l;
    pack2(v.x, v.y, h, l);
    *(uint32_t*)(hib + row * PBB + dp * 4) = h;
    *(uint32_t*)(lob + row * PBB + dp * 4) = l;
}

// ======================= K0: pre-split K/V into swizzled tile images =======================
// gid bits: [2:0]=chunk c, [13:3]=s, [17:14]=h, [20:18]=b, [21]=kv. 2^22 threads.
__global__ void __launch_bounds__(256)
split_k0(const float* __restrict__ Kg, const float* __restrict__ Vg)
{
    int gid = blockIdx.x * 256 + threadIdx.x;
    int c  = gid & 7;
    int s  = (gid >> 3) & 2047;
    int h  = (gid >> 14) & 15;
    int bb = (gid >> 18) & 7;
    int kv = gid >> 21;

    const float* src = (kv ? Vg : Kg) + ((size_t)bb * Sv + s) * Dm + h * DH + c * 8;
    float4 f0 = *(const float4*)src;
    float4 f1 = *(const float4*)(src + 4);
    uint32_t h0, l0, h1, l1, h2, l2, h3, l3;
    pack2(f0.x, f0.y, h0, l0);
    pack2(f0.z, f0.w, h1, l1);
    pack2(f1.x, f1.y, h2, l2);
    pack2(f1.z, f1.w, h3, l3);

    int tile = s >> 6, row = s & 63;
    int cph  = c ^ (row & 7);                       // XOR swizzle
    size_t base = ((((size_t)(bb * Hv + h) * NTILES + tile) * 4 + kv * 2)) * 8192
                + row * 128 + cph * 16;
    *(uint4*)(g_kv + base)        = make_uint4(h0, h1, h2, h3);   // hi image
    *(uint4*)(g_kv + base + 8192) = make_uint4(l0, l1, l2, l3);   // lo image
}

// ======================= K1: fused attention =======================
extern __shared__ char smem[];

__global__ void __launch_bounds__(NTH, 2)
attn_k1(const float* __restrict__ Qg, const int* __restrict__ Mg,
        float* __restrict__ outg, float* __restrict__ attng)
{
    const int tid  = threadIdx.x;
    const int lane = tid & 31;
    const int wq   = tid >> 5;          // warp -> q rows [wq*16, wq*16+16)
    const int q0   = blockIdx.x * MT;
    const int h    = blockIdx.y;
    const int b    = blockIdx.z;

    const uint32_t sb = su32(smem);
    unsigned char* mk = (unsigned char*)(smem + SM_MASK);

    const unsigned char* kvbase = g_kv + (size_t)(b * Hv + h) * NTILES * 32768;

    // ---- prime tile 0 (32 KB image) so it flies during Q/mask prologue ----
    #pragma unroll
    for (int it = 0; it < 8; it++) {
        int idx = tid + it * NTH;                  // 0..2047 chunks of 16B
        cp_async16(sb + SM_KV + idx * 16, kvbase + idx * 16);
    }
    CP_COMMIT();

    // Q scale folds 1/sqrt(Dh)=0.125 and log2(e): exp(s) == exp2(s_scaled)
    const float QSCALE = 0.125f * 1.44269504088896f;

    // ---- prologue: Q (scaled, hi/lo split) + mask ----
    #pragma unroll 4
    for (int it = 0; it < 16; it++) {
        int idx = tid + it * NTH;
        int m = idx >> 5, dp = idx & 31;
        float2 v = *(const float2*)(Qg + ((size_t)(b * Qv + q0 + m)) * Dm + h * DH + dp * 2);
        v.x *= QSCALE; v.y *= QSCALE;
        split_store(smem + SM_QHI, smem + SM_QLO, m, dp, v);
    }
    for (int s = tid; s < Sv; s += NTH)
        mk[s] = (unsigned char)Mg[(size_t)b * Sv + s];

    // ---- per-thread addresses ----
    // A (Q, pitch-144, unswizzled) -- unchanged, verified
    const uint32_t aAoff = (uint32_t)((wq * 16 + (lane & 15)) * PBB + ((lane & 16) >> 4) * 16);
    const uint32_t aAhi = sb + SM_QHI + aAoff;
    const uint32_t aAlo = sb + SM_QLO + aAoff;

    // B (K/V, pitch-128 swizzled images)
    const int s7 = lane & 7;
    const int cb = (lane & 8) >> 3;                 // K col half
    const int vb = (lane >> 4) & 1;                 // V col half
    const uint32_t rowK = (uint32_t)((lane & 7) + ((lane & 16) >> 1)) * 128;
    const uint32_t rowV = (uint32_t)((lane & 7) + (lane & 8)) * 128;
    uint32_t kc[4], vc[4];
    #pragma unroll
    for (int k4 = 0; k4 < 4; k4++) kc[k4] = (uint32_t)((((k4 << 1) | cb) ^ s7) << 4);
    #pragma unroll
    for (int np = 0; np < 4; np++) vc[np] = (uint32_t)((((np << 1) | vb) ^ s7) << 4);

    const int r = lane >> 2, c = lane & 3;

    float O[8][4];
    #pragma unroll
    for (int nt = 0; nt < 8; nt++)
        #pragma unroll
        for (int j = 0; j < 4; j++) O[nt][j] = 0.0f;
    float rsl = 0.0f, rsh = 0.0f;

    // attn row bases for direct fragment writes
    float* arow0 = attng + (((size_t)(b * Qv + q0 + wq * 16 + r)) * Hv + h) * Sv;
    float* arow1 = attng + (((size_t)(b * Qv + q0 + wq * 16 + r + 8)) * Hv + h) * Sv;

    for (int i = 0; i < NTILES; i++) {
        CP_WAIT0();
        __syncthreads();   // tile i image visible; buf[(i+1)&1] free (tile i-1 MMA done)

        // ---- issue cp for tile i+1 into the other buffer ----
        if (i + 1 < NTILES) {
            const unsigned char* g = kvbase + (size_t)(i + 1) * 32768;
            uint32_t dst = sb + SM_KV + ((i + 1) & 1) * 32768;
            #pragma unroll
            for (int it = 0; it < 8; it++) {
                int idx = tid + it * NTH;
                cp_async16(dst + idx * 16, g + idx * 16);
            }
        }
        CP_COMMIT();

        const uint32_t bufK = sb + SM_KV + (i & 1) * 32768;   // Khi | Klo(+8192) | Vhi(+16384) | Vlo(+24576)

        // ---- MMA1: S = Qs @ K^T (hi*hi + hi*lo + lo*hi) ----
        float S[8][4];
        #pragma unroll
        for (int nt = 0; nt < 8; nt++)
            #pragma unroll
            for (int j = 0; j < 4; j++) S[nt][j] = 0.0f;

        #pragma unroll
        for (int k4 = 0; k4 < 4; k4++) {
            uint32_t ah[4], al[4];
            ldm4(ah, aAhi + k4 * 32);
            ldm4(al, aAlo + k4 * 32);
            #pragma unroll
            for (int np = 0; np < 4; np++) {
                uint32_t bo = rowK + np * 2048 + kc[k4];
                uint32_t bh[4], bl[4];
                ldm4(bh, bufK + bo);
                ldm4(bl, bufK + 8192 + bo);
                mma16816(S[2*np],   ah, bh[0], bh[1]);
                mma16816(S[2*np+1], ah, bh[2], bh[3]);
                mma16816(S[2*np],   ah, bl[0], bl[1]);
                mma16816(S[2*np+1], ah, bl[2], bl[3]);
                mma16816(S[2*np],   al, bh[0], bh[1]);
                mma16816(S[2*np+1], al, bh[2], bh[3]);
            }
        }

        // ---- mask * exp2, rowsum, direct coalesced attn write (32B sectors) ----
        const int s0 = i * ST;
        #pragma unroll
        for (int nt = 0; nt < 8; nt++) {
            int col = nt * 8 + 2 * c;
            float m0 = (float)mk[s0 + col], m1 = (float)mk[s0 + col + 1];
            float e0 = m0 * exp2f(S[nt][0]);
            float e1 = m1 * exp2f(S[nt][1]);
            float e2 = m0 * exp2f(S[nt][2]);
            float e3 = m1 * exp2f(S[nt][3]);
            rsl += e0 + e1; rsh += e2 + e3;
            S[nt][0] = e0; S[nt][1] = e1; S[nt][2] = e2; S[nt][3] = e3;
            *(float2*)(arow0 + s0 + col) = make_float2(e0, e1);
            *(float2*)(arow1 + s0 + col) = make_float2(e2, e3);
        }

        // ---- MMA2: O += P @ V (Phi*Vhi + Phi*Vlo + Plo*Vhi), P from registers ----
        const uint32_t bufV = bufK + 16384;
        #pragma unroll
        for (int kt = 0; kt < 4; kt++) {
            uint32_t ph[4], pl[4];
            pack2(S[2*kt][0],   S[2*kt][1],   ph[0], pl[0]);
            pack2(S[2*kt][2],   S[2*kt][3],   ph[1], pl[1]);
            pack2(S[2*kt+1][0], S[2*kt+1][1], ph[2], pl[2]);
            pack2(S[2*kt+1][2], S[2*kt+1][3], ph[3], pl[3]);
            #pragma unroll
            for (int np = 0; np < 4; np++) {
                uint32_t bo = rowV + kt * 2048 + vc[np];
                uint32_t vh4[4], vl4[4];
                ldm4t(vh4, bufV + bo);
                ldm4t(vl4, bufV + 8192 + bo);
                mma16816(O[2*np],   ph, vh4[0], vh4[1]);
                mma16816(O[2*np+1], ph, vh4[2], vh4[3]);
                mma16816(O[2*np],   ph, vl4[0], vl4[1]);
                mma16816(O[2*np+1], ph, vl4[2], vl4[3]);
                mma16816(O[2*np],   pl, vh4[0], vh4[1]);
                mma16816(O[2*np+1], pl, vh4[2], vh4[3]);
            }
        }
    }

    // ---- rowsum reduce, rinv, normalize O, write out ----
    rsl += __shfl_xor_sync(0xffffffffu, rsl, 1);
    rsl += __shfl_xor_sync(0xffffffffu, rsl, 2);
    rsh += __shfl_xor_sync(0xffffffffu, rsh, 1);
    rsh += __shfl_xor_sync(0xffffffffu, rsh, 2);
    const float il = 1.0f / (rsl + 1e-13f);
    const float ih = 1.0f / (rsh + 1e-13f);

    if (c == 0) {
        g_rinv[(size_t)(b * Qv + q0 + wq * 16 + r)     * Hv + h] = il;
        g_rinv[(size_t)(b * Qv + q0 + wq * 16 + r + 8) * Hv + h] = ih;
    }

    float* orow0 = outg + (size_t)(b * Qv + q0 + wq * 16 + r)     * Dm + h * DH;
    float* orow1 = outg + (size_t)(b * Qv + q0 + wq * 16 + r + 8) * Dm + h * DH;
    #pragma unroll
    for (int nt = 0; nt < 8; nt++) {
        int col = nt * 8 + 2 * c;
        *(float2*)(orow0 + col) = make_float2(O[nt][0] * il, O[nt][1] * il);
        *(float2*)(orow1 + col) = make_float2(O[nt][2] * ih, O[nt][3] * ih);
    }
}

// ======================= K3: rescale attention (at DRAM roofline) =======================
__global__ void __launch_bounds__(256)
rescale_k3(float* __restrict__ attn)
{
    size_t i4 = (size_t)blockIdx.x * 256 + threadIdx.x;   // float4 index
    float rinv = g_rinv[i4 >> 9];                         // 512 float4 per (b,q,h) row
    float4* p = (float4*)attn + i4;
    float4 v = *p;
    v.x *= rinv; v.y *= rinv; v.z *= rinv; v.w *= rinv;
    *p = v;
}

// ======================= launch =======================
extern "C" void kernel_launch(void* const* d_in, const int* in_sizes, int n_in,
                              void* d_out, int out_size)
{
    const float* Qg = (const float*)d_in[0];
    const float* Kg = (const float*)d_in[1];
    const float* Vg = (const float*)d_in[2];
    const int*   Mg = (const int*)d_in[3];

    float* outg  = (float*)d_out;                     // [B,Q,D]
    float* attng = outg + (size_t)Bv * Qv * Dm;       // [B,Q,H,S]

    // K0: pre-split K/V (2^22 threads)
    split_k0<<<(2u << 21) / 256, 256>>>(Kg, Vg);

    // K1: fused attention
    cudaFuncSetAttribute(attn_k1, cudaFuncAttributeMaxDynamicSharedMemorySize, SMEM_TOTAL);
    dim3 grid(Qv / MT, Hv, Bv);                       // (8,16,8) = 1024 CTAs
    attn_k1<<<grid, NTH, SMEM_TOTAL>>>(Qg, Mg, outg, attng);

    // K3: rescale attention
    size_t n4 = (size_t)Bv * Qv * Hv * Sv / 4;        // 67,108,864 float4
    rescale_k3<<<(unsigned)(n4 / 256), 256>>>(attng);
}

// round 12
// speedup vs baseline: 1.6867x; 1.2215x over previous
#include <cuda_runtime.h>
#include <cuda_fp16.h>
#include <cstdint>

// ---------------- problem constants ----------------
#define Bv 8
#define Qv 1024
#define Sv 2048
#define Dm 1024
#define Hv 16
#define DH 64
#define MT 128            // q rows per CTA
#define ST 64             // s per tile
#define NTILES (Sv / ST)  // 32
#define NTH 256

// Q tile pitch (fp16 bytes) -- proven conflict-free for A ldmatrix
#define PB  72
#define PBB (PB * 2)      // 144 B per row

// ---------------- smem layout (bytes) ----------------
#define SM_QHI   0
#define SM_QLO   (SM_QHI + MT * PBB)      // 18432
#define SM_MASK  (SM_QLO + MT * PBB)      // 36864 (2048 u8)
#define SM_KV    (SM_MASK + 2048)         // 38912: 2 bufs x 16384 (K 8K | V 8K)
#define SMEM_TOTAL (SM_KV + 2 * 16384)    // 71680 -> 2 CTAs/SM

// scratch: [b][h][tile][K|V][64 rows][128 B], XOR-swizzled 16B chunks  (64 MB)
__device__ __align__(16) unsigned char g_kv[(size_t)Bv * Hv * NTILES * 2 * ST * 128];
__device__ float g_rinv[Bv * Qv * Hv];

// ---------------- helpers ----------------
__device__ __forceinline__ uint32_t su32(const void* p) {
    uint32_t a;
    asm("{ .reg .u64 t; cvta.to.shared.u64 t, %1; cvt.u32.u64 %0, t; }" : "=r"(a) : "l"(p));
    return a;
}

__device__ __forceinline__ void cp_async16(uint32_t dst, const void* src) {
    asm volatile("cp.async.cg.shared.global [%0], [%1], 16;" :: "r"(dst), "l"(src));
}
#define CP_COMMIT() asm volatile("cp.async.commit_group;" ::: "memory")
#define CP_WAIT0()  asm volatile("cp.async.wait_group 0;" ::: "memory")

__device__ __forceinline__ void ldm4(uint32_t* r, uint32_t a) {
    asm volatile("ldmatrix.sync.aligned.m8n8.x4.shared.b16 {%0,%1,%2,%3}, [%4];"
        : "=r"(r[0]), "=r"(r[1]), "=r"(r[2]), "=r"(r[3]) : "r"(a));
}
__device__ __forceinline__ void ldm4t(uint32_t* r, uint32_t a) {
    asm volatile("ldmatrix.sync.aligned.m8n8.x4.trans.shared.b16 {%0,%1,%2,%3}, [%4];"
        : "=r"(r[0]), "=r"(r[1]), "=r"(r[2]), "=r"(r[3]) : "r"(a));
}
__device__ __forceinline__ void mma16816(float* d, const uint32_t* a, uint32_t b0, uint32_t b1) {
    asm volatile("mma.sync.aligned.m16n8k16.row.col.f32.f16.f16.f32 "
        "{%0,%1,%2,%3}, {%4,%5,%6,%7}, {%8,%9}, {%0,%1,%2,%3};"
        : "+f"(d[0]), "+f"(d[1]), "+f"(d[2]), "+f"(d[3])
        : "r"(a[0]), "r"(a[1]), "r"(a[2]), "r"(a[3]), "r"(b0), "r"(b1));
}

// pack two fp32 into fp16x2 hi + fp16x2 lo (split); lo falls into subnormal
// fp16 range which tensor cores handle exactly.
__device__ __forceinline__ void pack2h(float e0, float e1, uint32_t& hi, uint32_t& lo) {
    __half2 h = __floats2half2_rn(e0, e1);
    hi = *(uint32_t*)&h;
    float f0 = __low2float(h), f1 = __high2float(h);
    __half2 l = __floats2half2_rn(e0 - f0, e1 - f1);
    lo = *(uint32_t*)&l;
}

// split a float2 into hi/lo fp16x2 tiles at (row, dpair) -- Q prologue only
__device__ __forceinline__ void split_store(char* hib, char* lob, int row, int dp, float2 v) {
    uint32_t h, l;
    pack2h(v.x, v.y, h, l);
    *(uint32_t*)(hib + row * PBB + dp * 4) = h;
    *(uint32_t*)(lob + row * PBB + dp * 4) = l;
}

// ======================= K0: pre-convert K/V to fp16 swizzled tile images =======================
// gid bits: [2:0]=chunk c (8/row), [13:3]=s, [17:14]=h, [20:18]=b, [21]=kv. 2^22 threads.
__global__ void __launch_bounds__(256)
split_k0(const float* __restrict__ Kg, const float* __restrict__ Vg)
{
    int gid = blockIdx.x * 256 + threadIdx.x;
    int c  = gid & 7;
    int s  = (gid >> 3) & 2047;
    int h  = (gid >> 14) & 15;
    int bb = (gid >> 18) & 7;
    int kv = gid >> 21;

    const float* src = (kv ? Vg : Kg) + ((size_t)bb * Sv + s) * Dm + h * DH + c * 8;
    float4 f0 = *(const float4*)src;
    float4 f1 = *(const float4*)(src + 4);
    __half2 h0 = __floats2half2_rn(f0.x, f0.y);
    __half2 h1 = __floats2half2_rn(f0.z, f0.w);
    __half2 h2 = __floats2half2_rn(f1.x, f1.y);
    __half2 h3 = __floats2half2_rn(f1.z, f1.w);

    int tile = s >> 6, row = s & 63;
    int cph  = c ^ (row & 7);                       // XOR swizzle
    size_t base = (((size_t)(bb * Hv + h) * NTILES + tile) * 2 + kv) * 8192
                + row * 128 + cph * 16;
    *(uint4*)(g_kv + base) = make_uint4(*(uint32_t*)&h0, *(uint32_t*)&h1,
                                        *(uint32_t*)&h2, *(uint32_t*)&h3);
}

// ======================= K1: fused attention =======================
extern __shared__ char smem[];

__global__ void __launch_bounds__(NTH, 2)
attn_k1(const float* __restrict__ Qg, const int* __restrict__ Mg,
        float* __restrict__ outg, float* __restrict__ attng)
{
    const int tid  = threadIdx.x;
    const int lane = tid & 31;
    const int wq   = tid >> 5;          // warp -> q rows [wq*16, wq*16+16)
    const int q0   = blockIdx.x * MT;
    const int h    = blockIdx.y;
    const int b    = blockIdx.z;

    const uint32_t sb = su32(smem);
    unsigned char* mk = (unsigned char*)(smem + SM_MASK);

    const unsigned char* kvbase = g_kv + (size_t)(b * Hv + h) * NTILES * 16384;

    // ---- prime tile 0 (16 KB image) so it flies during Q/mask prologue ----
    #pragma unroll
    for (int it = 0; it < 4; it++) {
        int idx = tid + it * NTH;                  // 0..1023 chunks of 16B
        cp_async16(sb + SM_KV + idx * 16, kvbase + idx * 16);
    }
    CP_COMMIT();

    // Q scale folds 1/sqrt(Dh)=0.125 and log2(e): exp(s) == exp2(s_scaled)
    const float QSCALE = 0.125f * 1.44269504088896f;

    // ---- prologue: Q (scaled, fp16 hi/lo split) + mask ----
    #pragma unroll 4
    for (int it = 0; it < 16; it++) {
        int idx = tid + it * NTH;
        int m = idx >> 5, dp = idx & 31;
        float2 v = *(const float2*)(Qg + ((size_t)(b * Qv + q0 + m)) * Dm + h * DH + dp * 2);
        v.x *= QSCALE; v.y *= QSCALE;
        split_store(smem + SM_QHI, smem + SM_QLO, m, dp, v);
    }
    for (int s = tid; s < Sv; s += NTH)
        mk[s] = (unsigned char)Mg[(size_t)b * Sv + s];

    // ---- per-thread addresses ----
    // A (Q, pitch-144, unswizzled)
    const uint32_t aAoff = (uint32_t)((wq * 16 + (lane & 15)) * PBB + ((lane & 16) >> 4) * 16);
    const uint32_t aAhi = sb + SM_QHI + aAoff;
    const uint32_t aAlo = sb + SM_QLO + aAoff;

    // B (K/V, pitch-128 swizzled images)
    const int s7 = lane & 7;
    const int cb = (lane & 8) >> 3;                 // K col half
    const int vb = (lane >> 4) & 1;                 // V col half
    const uint32_t rowK = (uint32_t)((lane & 7) + ((lane & 16) >> 1)) * 128;
    const uint32_t rowV = (uint32_t)((lane & 7) + (lane & 8)) * 128;
    uint32_t kc[4], vc[4];
    #pragma unroll
    for (int k4 = 0; k4 < 4; k4++) kc[k4] = (uint32_t)((((k4 << 1) | cb) ^ s7) << 4);
    #pragma unroll
    for (int np = 0; np < 4; np++) vc[np] = (uint32_t)((((np << 1) | vb) ^ s7) << 4);

    const int r = lane >> 2, c = lane & 3;

    float O[8][4];
    #pragma unroll
    for (int nt = 0; nt < 8; nt++)
        #pragma unroll
        for (int j = 0; j < 4; j++) O[nt][j] = 0.0f;
    float rsl = 0.0f, rsh = 0.0f;

    // attn row bases for direct fragment writes
    float* arow0 = attng + (((size_t)(b * Qv + q0 + wq * 16 + r)) * Hv + h) * Sv;
    float* arow1 = attng + (((size_t)(b * Qv + q0 + wq * 16 + r + 8)) * Hv + h) * Sv;

    for (int i = 0; i < NTILES; i++) {
        CP_WAIT0();
        __syncthreads();   // tile i image visible; buf[(i+1)&1] free (tile i-1 MMA done)

        // ---- issue cp for tile i+1 into the other buffer ----
        if (i + 1 < NTILES) {
            const unsigned char* g = kvbase + (size_t)(i + 1) * 16384;
            uint32_t dst = sb + SM_KV + ((i + 1) & 1) * 16384;
            #pragma unroll
            for (int it = 0; it < 4; it++) {
                int idx = tid + it * NTH;
                cp_async16(dst + idx * 16, g + idx * 16);
            }
        }
        CP_COMMIT();

        const uint32_t bufK = sb + SM_KV + (i & 1) * 16384;   // K | V(+8192)

        // ---- MMA1: S = Q_hi·K + Q_lo·K  (K single fp16) ----
        float S[8][4];
        #pragma unroll
        for (int nt = 0; nt < 8; nt++)
            #pragma unroll
            for (int j = 0; j < 4; j++) S[nt][j] = 0.0f;

        #pragma unroll
        for (int k4 = 0; k4 < 4; k4++) {
            uint32_t ah[4], al[4];
            ldm4(ah, aAhi + k4 * 32);
            ldm4(al, aAlo + k4 * 32);
            #pragma unroll
            for (int np = 0; np < 4; np++) {
                uint32_t bo = rowK + np * 2048 + kc[k4];
                uint32_t bk[4];
                ldm4(bk, bufK + bo);
                mma16816(S[2*np],   ah, bk[0], bk[1]);
                mma16816(S[2*np+1], ah, bk[2], bk[3]);
                mma16816(S[2*np],   al, bk[0], bk[1]);
                mma16816(S[2*np+1], al, bk[2], bk[3]);
            }
        }

        // ---- mask * exp2, rowsum, direct coalesced attn write (32B sectors) ----
        const int s0 = i * ST;
        #pragma unroll
        for (int nt = 0; nt < 8; nt++) {
            int col = nt * 8 + 2 * c;
            float m0 = (float)mk[s0 + col], m1 = (float)mk[s0 + col + 1];
            float e0 = m0 * exp2f(S[nt][0]);
            float e1 = m1 * exp2f(S[nt][1]);
            float e2 = m0 * exp2f(S[nt][2]);
            float e3 = m1 * exp2f(S[nt][3]);
            rsl += e0 + e1; rsh += e2 + e3;
            S[nt][0] = e0; S[nt][1] = e1; S[nt][2] = e2; S[nt][3] = e3;
            *(float2*)(arow0 + s0 + col) = make_float2(e0, e1);
            *(float2*)(arow1 + s0 + col) = make_float2(e2, e3);
        }

        // ---- MMA2: O += P_hi·V + P_lo·V  (V single fp16), P from registers ----
        const uint32_t bufV = bufK + 8192;
        #pragma unroll
        for (int kt = 0; kt < 4; kt++) {
            uint32_t ph[4], pl[4];
            pack2h(S[2*kt][0],   S[2*kt][1],   ph[0], pl[0]);
            pack2h(S[2*kt][2],   S[2*kt][3],   ph[1], pl[1]);
            pack2h(S[2*kt+1][0], S[2*kt+1][1], ph[2], pl[2]);
            pack2h(S[2*kt+1][2], S[2*kt+1][3], ph[3], pl[3]);
            #pragma unroll
            for (int np = 0; np < 4; np++) {
                uint32_t bo = rowV + kt * 2048 + vc[np];
                uint32_t v4[4];
                ldm4t(v4, bufV + bo);
                mma16816(O[2*np],   ph, v4[0], v4[1]);
                mma16816(O[2*np+1], ph, v4[2], v4[3]);
                mma16816(O[2*np],   pl, v4[0], v4[1]);
                mma16816(O[2*np+1], pl, v4[2], v4[3]);
            }
        }
    }

    // ---- rowsum reduce, rinv, normalize O, write out ----
    rsl += __shfl_xor_sync(0xffffffffu, rsl, 1);
    rsl += __shfl_xor_sync(0xffffffffu, rsl, 2);
    rsh += __shfl_xor_sync(0xffffffffu, rsh, 1);
    rsh += __shfl_xor_sync(0xffffffffu, rsh, 2);
    const float il = 1.0f / (rsl + 1e-13f);
    const float ih = 1.0f / (rsh + 1e-13f);

    if (c == 0) {
        g_rinv[(size_t)(b * Qv + q0 + wq * 16 + r)     * Hv + h] = il;
        g_rinv[(size_t)(b * Qv + q0 + wq * 16 + r + 8) * Hv + h] = ih;
    }

    float* orow0 = outg + (size_t)(b * Qv + q0 + wq * 16 + r)     * Dm + h * DH;
    float* orow1 = outg + (size_t)(b * Qv + q0 + wq * 16 + r + 8) * Dm + h * DH;
    #pragma unroll
    for (int nt = 0; nt < 8; nt++) {
        int col = nt * 8 + 2 * c;
        *(float2*)(orow0 + col) = make_float2(O[nt][0] * il, O[nt][1] * il);
        *(float2*)(orow1 + col) = make_float2(O[nt][2] * ih, O[nt][3] * ih);
    }
}

// ======================= K3: rescale attention (at DRAM roofline) =======================
__global__ void __launch_bounds__(256)
rescale_k3(float* __restrict__ attn)
{
    size_t i4 = (size_t)blockIdx.x * 256 + threadIdx.x;   // float4 index
    float rinv = g_rinv[i4 >> 9];                         // 512 float4 per (b,q,h) row
    float4* p = (float4*)attn + i4;
    float4 v = *p;
    v.x *= rinv; v.y *= rinv; v.z *= rinv; v.w *= rinv;
    *p = v;
}

// ======================= launch =======================
extern "C" void kernel_launch(void* const* d_in, const int* in_sizes, int n_in,
                              void* d_out, int out_size)
{
    const float* Qg = (const float*)d_in[0];
    const float* Kg = (const float*)d_in[1];
    const float* Vg = (const float*)d_in[2];
    const int*   Mg = (const int*)d_in[3];

    float* outg  = (float*)d_out;                     // [B,Q,D]
    float* attng = outg + (size_t)Bv * Qv * Dm;       // [B,Q,H,S]

    // K0: pre-convert K/V (2^22 threads)
    split_k0<<<(2u << 21) / 256, 256>>>(Kg, Vg);

    // K1: fused attention
    cudaFuncSetAttribute(attn_k1, cudaFuncAttributeMaxDynamicSharedMemorySize, SMEM_TOTAL);
    dim3 grid(Qv / MT, Hv, Bv);                       // (8,16,8) = 1024 CTAs
    attn_k1<<<grid, NTH, SMEM_TOTAL>>>(Qg, Mg, outg, attng);

    // K3: rescale attention
    size_t n4 = (size_t)Bv * Qv * Hv * Sv / 4;        // 67,108,864 float4
    rescale_k3<<<(unsigned)(n4 / 256), 256>>>(attng);
}

// round 13
// speedup vs baseline: 2.2293x; 1.3217x over previous
#include <cuda_runtime.h>
#include <cuda_fp16.h>
#include <cstdint>

// ---------------- problem constants ----------------
#define Bv 8
#define Qv 1024
#define Sv 2048
#define Dm 1024
#define Hv 16
#define DH 64
#define MT 128            // q rows per CTA
#define ST 64             // s per tile
#define NTILES (Sv / ST)  // 32
#define NTH 256

// Q tile pitch (fp16 bytes) -- proven conflict-free for A ldmatrix
#define PB  72
#define PBB (PB * 2)      // 144 B per row

// ---------------- smem layout (bytes) ----------------
#define SM_QHI   0
#define SM_QLO   (SM_QHI + MT * PBB)      // 18432
#define SM_MASK  (SM_QLO + MT * PBB)      // 36864 (2048 u8)
#define SM_KV    (SM_MASK + 2048)         // 38912: 2 bufs x 16384 (K 8K | V 8K)
#define SMEM_TOTAL (SM_KV + 2 * 16384)    // 71680 -> 2 CTAs/SM

// scratch: [b][h][tile][K|V][64 rows][128 B], XOR-swizzled 16B chunks  (64 MB)
__device__ __align__(16) unsigned char g_kv[(size_t)Bv * Hv * NTILES * 2 * ST * 128];

// ---------------- helpers ----------------
__device__ __forceinline__ uint32_t su32(const void* p) {
    uint32_t a;
    asm("{ .reg .u64 t; cvta.to.shared.u64 t, %1; cvt.u32.u64 %0, t; }" : "=r"(a) : "l"(p));
    return a;
}

__device__ __forceinline__ void cp_async16(uint32_t dst, const void* src) {
    asm volatile("cp.async.cg.shared.global [%0], [%1], 16;" :: "r"(dst), "l"(src));
}
#define CP_COMMIT() asm volatile("cp.async.commit_group;" ::: "memory")
#define CP_WAIT0()  asm volatile("cp.async.wait_group 0;" ::: "memory")

__device__ __forceinline__ void ldm4(uint32_t* r, uint32_t a) {
    asm volatile("ldmatrix.sync.aligned.m8n8.x4.shared.b16 {%0,%1,%2,%3}, [%4];"
        : "=r"(r[0]), "=r"(r[1]), "=r"(r[2]), "=r"(r[3]) : "r"(a));
}
__device__ __forceinline__ void ldm4t(uint32_t* r, uint32_t a) {
    asm volatile("ldmatrix.sync.aligned.m8n8.x4.trans.shared.b16 {%0,%1,%2,%3}, [%4];"
        : "=r"(r[0]), "=r"(r[1]), "=r"(r[2]), "=r"(r[3]) : "r"(a));
}
__device__ __forceinline__ void mma16816(float* d, const uint32_t* a, uint32_t b0, uint32_t b1) {
    asm volatile("mma.sync.aligned.m16n8k16.row.col.f32.f16.f16.f32 "
        "{%0,%1,%2,%3}, {%4,%5,%6,%7}, {%8,%9}, {%0,%1,%2,%3};"
        : "+f"(d[0]), "+f"(d[1]), "+f"(d[2]), "+f"(d[3])
        : "r"(a[0]), "r"(a[1]), "r"(a[2]), "r"(a[3]), "r"(b0), "r"(b1));
}

// pack two fp32 into fp16x2 hi + fp16x2 lo (split); lo falls into subnormal
// fp16 range which tensor cores handle exactly.
__device__ __forceinline__ void pack2h(float e0, float e1, uint32_t& hi, uint32_t& lo) {
    __half2 h = __floats2half2_rn(e0, e1);
    hi = *(uint32_t*)&h;
    float f0 = __low2float(h), f1 = __high2float(h);
    __half2 l = __floats2half2_rn(e0 - f0, e1 - f1);
    lo = *(uint32_t*)&l;
}

// split a float2 into hi/lo fp16x2 tiles at (row, dpair) -- Q prologue only
__device__ __forceinline__ void split_store(char* hib, char* lob, int row, int dp, float2 v) {
    uint32_t h, l;
    pack2h(v.x, v.y, h, l);
    *(uint32_t*)(hib + row * PBB + dp * 4) = h;
    *(uint32_t*)(lob + row * PBB + dp * 4) = l;
}

// ======================= K0: pre-convert K/V to fp16 swizzled tile images =======================
// gid bits: [2:0]=chunk c (8/row), [13:3]=s, [17:14]=h, [20:18]=b, [21]=kv. 2^22 threads.
__global__ void __launch_bounds__(256)
split_k0(const float* __restrict__ Kg, const float* __restrict__ Vg)
{
    int gid = blockIdx.x * 256 + threadIdx.x;
    int c  = gid & 7;
    int s  = (gid >> 3) & 2047;
    int h  = (gid >> 14) & 15;
    int bb = (gid >> 18) & 7;
    int kv = gid >> 21;

    const float* src = (kv ? Vg : Kg) + ((size_t)bb * Sv + s) * Dm + h * DH + c * 8;
    float4 f0 = *(const float4*)src;
    float4 f1 = *(const float4*)(src + 4);
    __half2 h0 = __floats2half2_rn(f0.x, f0.y);
    __half2 h1 = __floats2half2_rn(f0.z, f0.w);
    __half2 h2 = __floats2half2_rn(f1.x, f1.y);
    __half2 h3 = __floats2half2_rn(f1.z, f1.w);

    int tile = s >> 6, row = s & 63;
    int cph  = c ^ (row & 7);                       // XOR swizzle
    size_t base = (((size_t)(bb * Hv + h) * NTILES + tile) * 2 + kv) * 8192
                + row * 128 + cph * 16;
    *(uint4*)(g_kv + base) = make_uint4(*(uint32_t*)&h0, *(uint32_t*)&h1,
                                        *(uint32_t*)&h2, *(uint32_t*)&h3);
}

// ======================= K1: fused attention, two-pass (no K3) =======================
extern __shared__ char smem[];

__global__ void __launch_bounds__(NTH, 2)
attn_k1(const float* __restrict__ Qg, const int* __restrict__ Mg,
        float* __restrict__ outg, float* __restrict__ attng)
{
    const int tid  = threadIdx.x;
    const int lane = tid & 31;
    const int wq   = tid >> 5;          // warp -> q rows [wq*16, wq*16+16)
    const int q0   = blockIdx.x * MT;
    const int h    = blockIdx.y;
    const int b    = blockIdx.z;

    const uint32_t sb = su32(smem);
    unsigned char* mk = (unsigned char*)(smem + SM_MASK);

    const unsigned char* kvbase = g_kv + (size_t)(b * Hv + h) * NTILES * 16384;

    // ---- prime tile 0 (16 KB image) so it flies during Q/mask prologue ----
    #pragma unroll
    for (int it = 0; it < 4; it++) {
        int idx = tid + it * NTH;                  // 0..1023 chunks of 16B
        cp_async16(sb + SM_KV + idx * 16, kvbase + idx * 16);
    }
    CP_COMMIT();

    // Q scale folds 1/sqrt(Dh)=0.125 and log2(e): exp(s) == exp2(s_scaled)
    const float QSCALE = 0.125f * 1.44269504088896f;

    // ---- prologue: Q (scaled, fp16 hi/lo split) + mask ----
    #pragma unroll 4
    for (int it = 0; it < 16; it++) {
        int idx = tid + it * NTH;
        int m = idx >> 5, dp = idx & 31;
        float2 v = *(const float2*)(Qg + ((size_t)(b * Qv + q0 + m)) * Dm + h * DH + dp * 2);
        v.x *= QSCALE; v.y *= QSCALE;
        split_store(smem + SM_QHI, smem + SM_QLO, m, dp, v);
    }
    for (int s = tid; s < Sv; s += NTH)
        mk[s] = (unsigned char)Mg[(size_t)b * Sv + s];

    // ---- per-thread addresses ----
    // A (Q, pitch-144, unswizzled)
    const uint32_t aAoff = (uint32_t)((wq * 16 + (lane & 15)) * PBB + ((lane & 16) >> 4) * 16);
    const uint32_t aAhi = sb + SM_QHI + aAoff;
    const uint32_t aAlo = sb + SM_QLO + aAoff;

    // B (K/V, pitch-128 swizzled images)
    const int s7 = lane & 7;
    const int cb = (lane & 8) >> 3;                 // K col half
    const int vb = (lane >> 4) & 1;                 // V col half
    const uint32_t rowK = (uint32_t)((lane & 7) + ((lane & 16) >> 1)) * 128;
    const uint32_t rowV = (uint32_t)((lane & 7) + (lane & 8)) * 128;
    uint32_t kc[4], vc[4];
    #pragma unroll
    for (int k4 = 0; k4 < 4; k4++) kc[k4] = (uint32_t)((((k4 << 1) | cb) ^ s7) << 4);
    #pragma unroll
    for (int np = 0; np < 4; np++) vc[np] = (uint32_t)((((np << 1) | vb) ^ s7) << 4);

    const int r = lane >> 2, c = lane & 3;

    float O[8][4];
    #pragma unroll
    for (int nt = 0; nt < 8; nt++)
        #pragma unroll
        for (int j = 0; j < 4; j++) O[nt][j] = 0.0f;
    float rsl = 0.0f, rsh = 0.0f;

    // ================= PASS A: rowsums + O (no attn writes) =================
    for (int i = 0; i < NTILES; i++) {
        CP_WAIT0();
        __syncthreads();   // tile i image visible; buf[(i+1)&1] free

        if (i + 1 < NTILES) {
            const unsigned char* g = kvbase + (size_t)(i + 1) * 16384;
            uint32_t dst = sb + SM_KV + ((i + 1) & 1) * 16384;
            #pragma unroll
            for (int it = 0; it < 4; it++) {
                int idx = tid + it * NTH;
                cp_async16(dst + idx * 16, g + idx * 16);
            }
        }
        CP_COMMIT();

        const uint32_t bufK = sb + SM_KV + (i & 1) * 16384;   // K | V(+8192)

        // MMA1: S = Q_hi·K + Q_lo·K
        float S[8][4];
        #pragma unroll
        for (int nt = 0; nt < 8; nt++)
            #pragma unroll
            for (int j = 0; j < 4; j++) S[nt][j] = 0.0f;

        #pragma unroll
        for (int k4 = 0; k4 < 4; k4++) {
            uint32_t ah[4], al[4];
            ldm4(ah, aAhi + k4 * 32);
            ldm4(al, aAlo + k4 * 32);
            #pragma unroll
            for (int np = 0; np < 4; np++) {
                uint32_t bo = rowK + np * 2048 + kc[k4];
                uint32_t bk[4];
                ldm4(bk, bufK + bo);
                mma16816(S[2*np],   ah, bk[0], bk[1]);
                mma16816(S[2*np+1], ah, bk[2], bk[3]);
                mma16816(S[2*np],   al, bk[0], bk[1]);
                mma16816(S[2*np+1], al, bk[2], bk[3]);
            }
        }

        // mask * exp2 + rowsum (no store)
        const int s0 = i * ST;
        #pragma unroll
        for (int nt = 0; nt < 8; nt++) {
            int col = nt * 8 + 2 * c;
            float m0 = (float)mk[s0 + col], m1 = (float)mk[s0 + col + 1];
            float e0 = m0 * exp2f(S[nt][0]);
            float e1 = m1 * exp2f(S[nt][1]);
            float e2 = m0 * exp2f(S[nt][2]);
            float e3 = m1 * exp2f(S[nt][3]);
            rsl += e0 + e1; rsh += e2 + e3;
            S[nt][0] = e0; S[nt][1] = e1; S[nt][2] = e2; S[nt][3] = e3;
        }

        // MMA2: O += P_hi·V + P_lo·V
        const uint32_t bufV = bufK + 8192;
        #pragma unroll
        for (int kt = 0; kt < 4; kt++) {
            uint32_t ph[4], pl[4];
            pack2h(S[2*kt][0],   S[2*kt][1],   ph[0], pl[0]);
            pack2h(S[2*kt][2],   S[2*kt][3],   ph[1], pl[1]);
            pack2h(S[2*kt+1][0], S[2*kt+1][1], ph[2], pl[2]);
            pack2h(S[2*kt+1][2], S[2*kt+1][3], ph[3], pl[3]);
            #pragma unroll
            for (int np = 0; np < 4; np++) {
                uint32_t bo = rowV + kt * 2048 + vc[np];
                uint32_t v4[4];
                ldm4t(v4, bufV + bo);
                mma16816(O[2*np],   ph, v4[0], v4[1]);
                mma16816(O[2*np+1], ph, v4[2], v4[3]);
                mma16816(O[2*np],   pl, v4[0], v4[1]);
                mma16816(O[2*np+1], pl, v4[2], v4[3]);
            }
        }
    }

    // ---- prime pass B tile 0 (K image only, 8 KB) into buf0 ----
    // (buf0 last read at tile 30; the i=31 top-sync proves all warps are past it)
    #pragma unroll
    for (int it = 0; it < 2; it++) {
        int idx = tid + it * NTH;                  // 0..511 chunks
        cp_async16(sb + SM_KV + idx * 16, kvbase + idx * 16);
    }
    CP_COMMIT();

    // ---- rowsum reduce, rinv, normalize O, write out (overlaps tile-0 fetch) ----
    rsl += __shfl_xor_sync(0xffffffffu, rsl, 1);
    rsl += __shfl_xor_sync(0xffffffffu, rsl, 2);
    rsh += __shfl_xor_sync(0xffffffffu, rsh, 1);
    rsh += __shfl_xor_sync(0xffffffffu, rsh, 2);
    const float il = 1.0f / (rsl + 1e-13f);
    const float ih = 1.0f / (rsh + 1e-13f);

    float* orow0 = outg + (size_t)(b * Qv + q0 + wq * 16 + r)     * Dm + h * DH;
    float* orow1 = outg + (size_t)(b * Qv + q0 + wq * 16 + r + 8) * Dm + h * DH;
    #pragma unroll
    for (int nt = 0; nt < 8; nt++) {
        int col = nt * 8 + 2 * c;
        *(float2*)(orow0 + col) = make_float2(O[nt][0] * il, O[nt][1] * il);
        *(float2*)(orow1 + col) = make_float2(O[nt][2] * ih, O[nt][3] * ih);
    }

    // ================= PASS B: recompute scores (1-pass), write normalized attn =================
    float* arow0 = attng + (((size_t)(b * Qv + q0 + wq * 16 + r)) * Hv + h) * Sv;
    float* arow1 = attng + (((size_t)(b * Qv + q0 + wq * 16 + r + 8)) * Hv + h) * Sv;

    for (int i = 0; i < NTILES; i++) {
        CP_WAIT0();
        __syncthreads();   // K image for tile i visible; other buf free

        if (i + 1 < NTILES) {
            const unsigned char* g = kvbase + (size_t)(i + 1) * 16384;
            uint32_t dst = sb + SM_KV + ((i + 1) & 1) * 16384;
            #pragma unroll
            for (int it = 0; it < 2; it++) {
                int idx = tid + it * NTH;
                cp_async16(dst + idx * 16, g + idx * 16);
            }
        }
        CP_COMMIT();

        const uint32_t bufK = sb + SM_KV + (i & 1) * 16384;

        // MMA1 single-pass: S = Q_hi·K
        float S[8][4];
        #pragma unroll
        for (int nt = 0; nt < 8; nt++)
            #pragma unroll
            for (int j = 0; j < 4; j++) S[nt][j] = 0.0f;

        #pragma unroll
        for (int k4 = 0; k4 < 4; k4++) {
            uint32_t ah[4];
            ldm4(ah, aAhi + k4 * 32);
            #pragma unroll
            for (int np = 0; np < 4; np++) {
                uint32_t bo = rowK + np * 2048 + kc[k4];
                uint32_t bk[4];
                ldm4(bk, bufK + bo);
                mma16816(S[2*np],   ah, bk[0], bk[1]);
                mma16816(S[2*np+1], ah, bk[2], bk[3]);
            }
        }

        // normalized attn = m * exp2(S) * rinv, direct coalesced write
        const int s0 = i * ST;
        #pragma unroll
        for (int nt = 0; nt < 8; nt++) {
            int col = nt * 8 + 2 * c;
            float m0 = il * (float)mk[s0 + col], m1 = il * (float)mk[s0 + col + 1];
            float n0 = ih * (float)mk[s0 + col], n1 = ih * (float)mk[s0 + col + 1];
            *(float2*)(arow0 + s0 + col) =
                make_float2(m0 * exp2f(S[nt][0]), m1 * exp2f(S[nt][1]));
            *(float2*)(arow1 + s0 + col) =
                make_float2(n0 * exp2f(S[nt][2]), n1 * exp2f(S[nt][3]));
        }
    }
}

// ======================= launch =======================
extern "C" void kernel_launch(void* const* d_in, const int* in_sizes, int n_in,
                              void* d_out, int out_size)
{
    const float* Qg = (const float*)d_in[0];
    const float* Kg = (const float*)d_in[1];
    const float* Vg = (const float*)d_in[2];
    const int*   Mg = (const int*)d_in[3];

    float* outg  = (float*)d_out;                     // [B,Q,D]
    float* attng = outg + (size_t)Bv * Qv * Dm;       // [B,Q,H,S]

    // K0: pre-convert K/V (2^22 threads)
    split_k0<<<(2u << 21) / 256, 256>>>(Kg, Vg);

    // K1: fused attention (two-pass, writes normalized attn directly)
    cudaFuncSetAttribute(attn_k1, cudaFuncAttributeMaxDynamicSharedMemorySize, SMEM_TOTAL);
    dim3 grid(Qv / MT, Hv, Bv);                       // (8,16,8) = 1024 CTAs
    attn_k1<<<grid, NTH, SMEM_TOTAL>>>(Qg, Mg, outg, attng);
}

// round 14
// speedup vs baseline: 2.4682x; 1.1072x over previous
#include <cuda_runtime.h>
#include <cuda_fp16.h>
#include <cstdint>

// ---------------- problem constants ----------------
#define Bv 8
#define Qv 1024
#define Sv 2048
#define Dm 1024
#define Hv 16
#define DH 64
#define MT 128            // q rows per CTA
#define ST 64             // s per tile
#define NTILES (Sv / ST)  // 32
#define NTH 256

// Q tile pitch (fp16 bytes) -- proven conflict-free for A ldmatrix
#define PB  72
#define PBB (PB * 2)      // 144 B per row

// ---------------- smem layout (bytes) ----------------
#define SM_QHI   0
#define SM_QLO   (SM_QHI + MT * PBB)      // 18432
#define SM_MASK  (SM_QLO + MT * PBB)      // 36864 (2048 u8)
#define SM_KV    (SM_MASK + 2048)         // 38912: 2 bufs x 16384 (K 8K | V 8K)
#define SMEM_TOTAL (SM_KV + 2 * 16384)    // 71680 -> 2 CTAs/SM

// scratch: [b][h][tile][K|V][64 rows][128 B], XOR-swizzled 16B chunks  (64 MB)
__device__ __align__(16) unsigned char g_kv[(size_t)Bv * Hv * NTILES * 2 * ST * 128];

// ---------------- helpers ----------------
__device__ __forceinline__ uint32_t su32(const void* p) {
    uint32_t a;
    asm("{ .reg .u64 t; cvta.to.shared.u64 t, %1; cvt.u32.u64 %0, t; }" : "=r"(a) : "l"(p));
    return a;
}

__device__ __forceinline__ void cp_async16(uint32_t dst, const void* src) {
    asm volatile("cp.async.cg.shared.global [%0], [%1], 16;" :: "r"(dst), "l"(src));
}
#define CP_COMMIT() asm volatile("cp.async.commit_group;" ::: "memory")
#define CP_WAIT0()  asm volatile("cp.async.wait_group 0;" ::: "memory")

__device__ __forceinline__ void ldm4(uint32_t* r, uint32_t a) {
    asm volatile("ldmatrix.sync.aligned.m8n8.x4.shared.b16 {%0,%1,%2,%3}, [%4];"
        : "=r"(r[0]), "=r"(r[1]), "=r"(r[2]), "=r"(r[3]) : "r"(a));
}
__device__ __forceinline__ void ldm4t(uint32_t* r, uint32_t a) {
    asm volatile("ldmatrix.sync.aligned.m8n8.x4.trans.shared.b16 {%0,%1,%2,%3}, [%4];"
        : "=r"(r[0]), "=r"(r[1]), "=r"(r[2]), "=r"(r[3]) : "r"(a));
}
__device__ __forceinline__ void mma16816(float* d, const uint32_t* a, uint32_t b0, uint32_t b1) {
    asm volatile("mma.sync.aligned.m16n8k16.row.col.f32.f16.f16.f32 "
        "{%0,%1,%2,%3}, {%4,%5,%6,%7}, {%8,%9}, {%0,%1,%2,%3};"
        : "+f"(d[0]), "+f"(d[1]), "+f"(d[2]), "+f"(d[3])
        : "r"(a[0]), "r"(a[1]), "r"(a[2]), "r"(a[3]), "r"(b0), "r"(b1));
}

// pack two fp32 into fp16x2 hi + fp16x2 lo (split); lo falls into subnormal
// fp16 range which tensor cores handle exactly.
__device__ __forceinline__ void pack2h(float e0, float e1, uint32_t& hi, uint32_t& lo) {
    __half2 h = __floats2half2_rn(e0, e1);
    hi = *(uint32_t*)&h;
    float f0 = __low2float(h), f1 = __high2float(h);
    __half2 l = __floats2half2_rn(e0 - f0, e1 - f1);
    lo = *(uint32_t*)&l;
}

// split a float2 into hi/lo fp16x2 tiles at (row, dpair) -- Q prologue only
__device__ __forceinline__ void split_store(char* hib, char* lob, int row, int dp, float2 v) {
    uint32_t h, l;
    pack2h(v.x, v.y, h, l);
    *(uint32_t*)(hib + row * PBB + dp * 4) = h;
    *(uint32_t*)(lob + row * PBB + dp * 4) = l;
}

// ======================= K0: pre-convert K/V to fp16 swizzled tile images =======================
// gid bits: [2:0]=chunk c (8/row), [13:3]=s, [17:14]=h, [20:18]=b, [21]=kv. 2^22 threads.
__global__ void __launch_bounds__(256)
split_k0(const float* __restrict__ Kg, const float* __restrict__ Vg)
{
    int gid = blockIdx.x * 256 + threadIdx.x;
    int c  = gid & 7;
    int s  = (gid >> 3) & 2047;
    int h  = (gid >> 14) & 15;
    int bb = (gid >> 18) & 7;
    int kv = gid >> 21;

    const float* src = (kv ? Vg : Kg) + ((size_t)bb * Sv + s) * Dm + h * DH + c * 8;
    float4 f0 = *(const float4*)src;
    float4 f1 = *(const float4*)(src + 4);
    __half2 h0 = __floats2half2_rn(f0.x, f0.y);
    __half2 h1 = __floats2half2_rn(f0.z, f0.w);
    __half2 h2 = __floats2half2_rn(f1.x, f1.y);
    __half2 h3 = __floats2half2_rn(f1.z, f1.w);

    int tile = s >> 6, row = s & 63;
    int cph  = c ^ (row & 7);                       // XOR swizzle
    size_t base = (((size_t)(bb * Hv + h) * NTILES + tile) * 2 + kv) * 8192
                + row * 128 + cph * 16;
    *(uint4*)(g_kv + base) = make_uint4(*(uint32_t*)&h0, *(uint32_t*)&h1,
                                        *(uint32_t*)&h2, *(uint32_t*)&h3);
}

// ======================= K1: fused attention, two-pass (no K3) =======================
extern __shared__ char smem[];

__global__ void __launch_bounds__(NTH, 2)
attn_k1(const float* __restrict__ Qg, const int* __restrict__ Mg,
        float* __restrict__ outg, float* __restrict__ attng)
{
    const int tid  = threadIdx.x;
    const int lane = tid & 31;
    const int wq   = tid >> 5;          // warp -> q rows [wq*16, wq*16+16)
    const int q0   = blockIdx.x * MT;
    const int h    = blockIdx.y;
    const int b    = blockIdx.z;

    const uint32_t sb = su32(smem);
    unsigned char* mk = (unsigned char*)(smem + SM_MASK);

    const unsigned char* kvbase = g_kv + (size_t)(b * Hv + h) * NTILES * 16384;

    // ---- prime tile 0 (16 KB image) so it flies during Q/mask prologue ----
    #pragma unroll
    for (int it = 0; it < 4; it++) {
        int idx = tid + it * NTH;                  // 0..1023 chunks of 16B
        cp_async16(sb + SM_KV + idx * 16, kvbase + idx * 16);
    }
    CP_COMMIT();

    // Q scale folds 1/sqrt(Dh)=0.125 and log2(e): exp(s) == exp2(s_scaled)
    const float QSCALE = 0.125f * 1.44269504088896f;

    // ---- prologue: Q (scaled, fp16 hi/lo split) + mask ----
    #pragma unroll 4
    for (int it = 0; it < 16; it++) {
        int idx = tid + it * NTH;
        int m = idx >> 5, dp = idx & 31;
        float2 v = *(const float2*)(Qg + ((size_t)(b * Qv + q0 + m)) * Dm + h * DH + dp * 2);
        v.x *= QSCALE; v.y *= QSCALE;
        split_store(smem + SM_QHI, smem + SM_QLO, m, dp, v);
    }
    for (int s = tid; s < Sv; s += NTH)
        mk[s] = (unsigned char)Mg[(size_t)b * Sv + s];

    // ---- per-thread addresses ----
    // A (Q, pitch-144, unswizzled)
    const uint32_t aAoff = (uint32_t)((wq * 16 + (lane & 15)) * PBB + ((lane & 16) >> 4) * 16);
    const uint32_t aAhi = sb + SM_QHI + aAoff;
    const uint32_t aAlo = sb + SM_QLO + aAoff;

    // B (K/V, pitch-128 swizzled images)
    const int s7 = lane & 7;
    const int cb = (lane & 8) >> 3;                 // K col half
    const int vb = (lane >> 4) & 1;                 // V col half
    const uint32_t rowK = (uint32_t)((lane & 7) + ((lane & 16) >> 1)) * 128;
    const uint32_t rowV = (uint32_t)((lane & 7) + (lane & 8)) * 128;
    uint32_t kc[4], vc[4];
    #pragma unroll
    for (int k4 = 0; k4 < 4; k4++) kc[k4] = (uint32_t)((((k4 << 1) | cb) ^ s7) << 4);
    #pragma unroll
    for (int np = 0; np < 4; np++) vc[np] = (uint32_t)((((np << 1) | vb) ^ s7) << 4);

    const int r = lane >> 2, c = lane & 3;

    float O[8][4];
    #pragma unroll
    for (int nt = 0; nt < 8; nt++)
        #pragma unroll
        for (int j = 0; j < 4; j++) O[nt][j] = 0.0f;
    float rsl = 0.0f, rsh = 0.0f;

    // ================= PASS A: rowsums + O (no attn writes) =================
    for (int i = 0; i < NTILES; i++) {
        CP_WAIT0();
        __syncthreads();   // tile i image visible; buf[(i+1)&1] free

        if (i + 1 < NTILES) {
            const unsigned char* g = kvbase + (size_t)(i + 1) * 16384;
            uint32_t dst = sb + SM_KV + ((i + 1) & 1) * 16384;
            #pragma unroll
            for (int it = 0; it < 4; it++) {
                int idx = tid + it * NTH;
                cp_async16(dst + idx * 16, g + idx * 16);
            }
        }
        CP_COMMIT();

        const uint32_t bufK = sb + SM_KV + (i & 1) * 16384;   // K | V(+8192)

        // MMA1: S = Q_hi·K + Q_lo·K (2-pass: rowsums must be accurate)
        float S[8][4];
        #pragma unroll
        for (int nt = 0; nt < 8; nt++)
            #pragma unroll
            for (int j = 0; j < 4; j++) S[nt][j] = 0.0f;

        #pragma unroll
        for (int k4 = 0; k4 < 4; k4++) {
            uint32_t ah[4], al[4];
            ldm4(ah, aAhi + k4 * 32);
            ldm4(al, aAlo + k4 * 32);
            #pragma unroll
            for (int np = 0; np < 4; np++) {
                uint32_t bo = rowK + np * 2048 + kc[k4];
                uint32_t bk[4];
                ldm4(bk, bufK + bo);
                mma16816(S[2*np],   ah, bk[0], bk[1]);
                mma16816(S[2*np+1], ah, bk[2], bk[3]);
                mma16816(S[2*np],   al, bk[0], bk[1]);
                mma16816(S[2*np+1], al, bk[2], bk[3]);
            }
        }

        // mask * exp2 + rowsum (no store)
        const int s0 = i * ST;
        #pragma unroll
        for (int nt = 0; nt < 8; nt++) {
            int col = nt * 8 + 2 * c;
            float m0 = (float)mk[s0 + col], m1 = (float)mk[s0 + col + 1];
            float e0 = m0 * exp2f(S[nt][0]);
            float e1 = m1 * exp2f(S[nt][1]);
            float e2 = m0 * exp2f(S[nt][2]);
            float e3 = m1 * exp2f(S[nt][3]);
            rsl += e0 + e1; rsh += e2 + e3;
            S[nt][0] = e0; S[nt][1] = e1; S[nt][2] = e2; S[nt][3] = e3;
        }

        // MMA2: O += P_hi·V  (single-pass: P rounded to fp16, rel err ~2^-12)
        const uint32_t bufV = bufK + 8192;
        #pragma unroll
        for (int kt = 0; kt < 4; kt++) {
            uint32_t ph[4];
            __half2 p0 = __floats2half2_rn(S[2*kt][0],   S[2*kt][1]);
            __half2 p1 = __floats2half2_rn(S[2*kt][2],   S[2*kt][3]);
            __half2 p2 = __floats2half2_rn(S[2*kt+1][0], S[2*kt+1][1]);
            __half2 p3 = __floats2half2_rn(S[2*kt+1][2], S[2*kt+1][3]);
            ph[0] = *(uint32_t*)&p0; ph[1] = *(uint32_t*)&p1;
            ph[2] = *(uint32_t*)&p2; ph[3] = *(uint32_t*)&p3;
            #pragma unroll
            for (int np = 0; np < 4; np++) {
                uint32_t bo = rowV + kt * 2048 + vc[np];
                uint32_t v4[4];
                ldm4t(v4, bufV + bo);
                mma16816(O[2*np],   ph, v4[0], v4[1]);
                mma16816(O[2*np+1], ph, v4[2], v4[3]);
            }
        }
    }

    // ---- prime pass B tile 0 (K image only, 8 KB) into buf0 ----
    #pragma unroll
    for (int it = 0; it < 2; it++) {
        int idx = tid + it * NTH;                  // 0..511 chunks
        cp_async16(sb + SM_KV + idx * 16, kvbase + idx * 16);
    }
    CP_COMMIT();

    // ---- rowsum reduce, rinv, normalize O, write out (overlaps tile-0 fetch) ----
    rsl += __shfl_xor_sync(0xffffffffu, rsl, 1);
    rsl += __shfl_xor_sync(0xffffffffu, rsl, 2);
    rsh += __shfl_xor_sync(0xffffffffu, rsh, 1);
    rsh += __shfl_xor_sync(0xffffffffu, rsh, 2);
    const float il = 1.0f / (rsl + 1e-13f);
    const float ih = 1.0f / (rsh + 1e-13f);

    float* orow0 = outg + (size_t)(b * Qv + q0 + wq * 16 + r)     * Dm + h * DH;
    float* orow1 = outg + (size_t)(b * Qv + q0 + wq * 16 + r + 8) * Dm + h * DH;
    #pragma unroll
    for (int nt = 0; nt < 8; nt++) {
        int col = nt * 8 + 2 * c;
        *(float2*)(orow0 + col) = make_float2(O[nt][0] * il, O[nt][1] * il);
        *(float2*)(orow1 + col) = make_float2(O[nt][2] * ih, O[nt][3] * ih);
    }

    // ================= PASS B: recompute scores (1-pass), write normalized attn =================
    float* arow0 = attng + (((size_t)(b * Qv + q0 + wq * 16 + r)) * Hv + h) * Sv;
    float* arow1 = attng + (((size_t)(b * Qv + q0 + wq * 16 + r + 8)) * Hv + h) * Sv;

    for (int i = 0; i < NTILES; i++) {
        CP_WAIT0();
        __syncthreads();   // K image for tile i visible; other buf free

        if (i + 1 < NTILES) {
            const unsigned char* g = kvbase + (size_t)(i + 1) * 16384;
            uint32_t dst = sb + SM_KV + ((i + 1) & 1) * 16384;
            #pragma unroll
            for (int it = 0; it < 2; it++) {
                int idx = tid + it * NTH;
                cp_async16(dst + idx * 16, g + idx * 16);
            }
        }
        CP_COMMIT();

        const uint32_t bufK = sb + SM_KV + (i & 1) * 16384;

        // MMA1 single-pass: S = Q_hi·K
        float S[8][4];
        #pragma unroll
        for (int nt = 0; nt < 8; nt++)
            #pragma unroll
            for (int j = 0; j < 4; j++) S[nt][j] = 0.0f;

        #pragma unroll
        for (int k4 = 0; k4 < 4; k4++) {
            uint32_t ah[4];
            ldm4(ah, aAhi + k4 * 32);
            #pragma unroll
            for (int np = 0; np < 4; np++) {
                uint32_t bo = rowK + np * 2048 + kc[k4];
                uint32_t bk[4];
                ldm4(bk, bufK + bo);
                mma16816(S[2*np],   ah, bk[0], bk[1]);
                mma16816(S[2*np+1], ah, bk[2], bk[3]);
            }
        }

        // normalized attn = m * exp2(S) * rinv, direct coalesced write
        const int s0 = i * ST;
        #pragma unroll
        for (int nt = 0; nt < 8; nt++) {
            int col = nt * 8 + 2 * c;
            float m0 = il * (float)mk[s0 + col], m1 = il * (float)mk[s0 + col + 1];
            float n0 = ih * (float)mk[s0 + col], n1 = ih * (float)mk[s0 + col + 1];
            *(float2*)(arow0 + s0 + col) =
                make_float2(m0 * exp2f(S[nt][0]), m1 * exp2f(S[nt][1]));
            *(float2*)(arow1 + s0 + col) =
                make_float2(n0 * exp2f(S[nt][2]), n1 * exp2f(S[nt][3]));
        }
    }
}

// ======================= launch =======================
extern "C" void kernel_launch(void* const* d_in, const int* in_sizes, int n_in,
                              void* d_out, int out_size)
{
    const float* Qg = (const float*)d_in[0];
    const float* Kg = (const float*)d_in[1];
    const float* Vg = (const float*)d_in[2];
    const int*   Mg = (const int*)d_in[3];

    float* outg  = (float*)d_out;                     // [B,Q,D]
    float* attng = outg + (size_t)Bv * Qv * Dm;       // [B,Q,H,S]

    // K0: pre-convert K/V (2^22 threads)
    split_k0<<<(2u << 21) / 256, 256>>>(Kg, Vg);

    // K1: fused attention (two-pass, writes normalized attn directly)
    cudaFuncSetAttribute(attn_k1, cudaFuncAttributeMaxDynamicSharedMemorySize, SMEM_TOTAL);
    dim3 grid(Qv / MT, Hv, Bv);                       // (8,16,8) = 1024 CTAs
    attn_k1<<<grid, NTH, SMEM_TOTAL>>>(Qg, Mg, outg, attng);
}

// round 15
// speedup vs baseline: 2.7022x; 1.0948x over previous
#include <cuda_runtime.h>
#include <cuda_fp16.h>
#include <cstdint>

// ---------------- problem constants ----------------
#define Bv 8
#define Qv 1024
#define Sv 2048
#define Dm 1024
#define Hv 16
#define DH 64
#define MT 128            // q rows per CTA
#define ST 64             // s per tile
#define NTILES (Sv / ST)  // 32
#define NTH 256

// Q tile pitch (fp16 bytes) -- proven conflict-free for A ldmatrix
#define PB  72
#define PBB (PB * 2)      // 144 B per row

// ---------------- smem layout (bytes) ----------------
#define SM_QHI   0
#define SM_MASK  (SM_QHI + MT * PBB)      // 18432 (2048 u8)
#define SM_KV    (SM_MASK + 2048)         // 20480: 2 bufs x 16384 (K 8K | V 8K)
#define SMEM_TOTAL (SM_KV + 2 * 16384)    // 53248 -> 2 CTAs/SM

// scratch: [b][h][tile][K|V][64 rows][128 B], XOR-swizzled 16B chunks  (64 MB)
__device__ __align__(16) unsigned char g_kv[(size_t)Bv * Hv * NTILES * 2 * ST * 128];

// ---------------- helpers ----------------
__device__ __forceinline__ uint32_t su32(const void* p) {
    uint32_t a;
    asm("{ .reg .u64 t; cvta.to.shared.u64 t, %1; cvt.u32.u64 %0, t; }" : "=r"(a) : "l"(p));
    return a;
}

__device__ __forceinline__ void cp_async16(uint32_t dst, const void* src) {
    asm volatile("cp.async.cg.shared.global [%0], [%1], 16;" :: "r"(dst), "l"(src));
}
#define CP_COMMIT() asm volatile("cp.async.commit_group;" ::: "memory")
#define CP_WAIT0()  asm volatile("cp.async.wait_group 0;" ::: "memory")

__device__ __forceinline__ void ldm4(uint32_t* r, uint32_t a) {
    asm volatile("ldmatrix.sync.aligned.m8n8.x4.shared.b16 {%0,%1,%2,%3}, [%4];"
        : "=r"(r[0]), "=r"(r[1]), "=r"(r[2]), "=r"(r[3]) : "r"(a));
}
__device__ __forceinline__ void ldm4t(uint32_t* r, uint32_t a) {
    asm volatile("ldmatrix.sync.aligned.m8n8.x4.trans.shared.b16 {%0,%1,%2,%3}, [%4];"
        : "=r"(r[0]), "=r"(r[1]), "=r"(r[2]), "=r"(r[3]) : "r"(a));
}
__device__ __forceinline__ void mma16816(float* d, const uint32_t* a, uint32_t b0, uint32_t b1) {
    asm volatile("mma.sync.aligned.m16n8k16.row.col.f32.f16.f16.f32 "
        "{%0,%1,%2,%3}, {%4,%5,%6,%7}, {%8,%9}, {%0,%1,%2,%3};"
        : "+f"(d[0]), "+f"(d[1]), "+f"(d[2]), "+f"(d[3])
        : "r"(a[0]), "r"(a[1]), "r"(a[2]), "r"(a[3]), "r"(b0), "r"(b1));
}

// ======================= K0: pre-convert K/V to fp16 swizzled tile images =======================
// gid bits: [2:0]=chunk c (8/row), [13:3]=s, [17:14]=h, [20:18]=b, [21]=kv. 2^22 threads.
__global__ void __launch_bounds__(256)
split_k0(const float* __restrict__ Kg, const float* __restrict__ Vg)
{
    int gid = blockIdx.x * 256 + threadIdx.x;
    int c  = gid & 7;
    int s  = (gid >> 3) & 2047;
    int h  = (gid >> 14) & 15;
    int bb = (gid >> 18) & 7;
    int kv = gid >> 21;

    const float* src = (kv ? Vg : Kg) + ((size_t)bb * Sv + s) * Dm + h * DH + c * 8;
    float4 f0 = *(const float4*)src;
    float4 f1 = *(const float4*)(src + 4);
    __half2 h0 = __floats2half2_rn(f0.x, f0.y);
    __half2 h1 = __floats2half2_rn(f0.z, f0.w);
    __half2 h2 = __floats2half2_rn(f1.x, f1.y);
    __half2 h3 = __floats2half2_rn(f1.z, f1.w);

    int tile = s >> 6, row = s & 63;
    int cph  = c ^ (row & 7);                       // XOR swizzle
    size_t base = (((size_t)(bb * Hv + h) * NTILES + tile) * 2 + kv) * 8192
                + row * 128 + cph * 16;
    *(uint4*)(g_kv + base) = make_uint4(*(uint32_t*)&h0, *(uint32_t*)&h1,
                                        *(uint32_t*)&h2, *(uint32_t*)&h3);
}

// ======================= K1: fused attention, two-pass, all single-pass fp16 =======================
extern __shared__ char smem[];

__global__ void __launch_bounds__(NTH, 2)
attn_k1(const float* __restrict__ Qg, const int* __restrict__ Mg,
        float* __restrict__ outg, float* __restrict__ attng)
{
    const int tid  = threadIdx.x;
    const int lane = tid & 31;
    const int wq   = tid >> 5;          // warp -> q rows [wq*16, wq*16+16)
    const int q0   = blockIdx.x * MT;
    const int h    = blockIdx.y;
    const int b    = blockIdx.z;

    const uint32_t sb = su32(smem);
    unsigned char* mk = (unsigned char*)(smem + SM_MASK);

    const unsigned char* kvbase = g_kv + (size_t)(b * Hv + h) * NTILES * 16384;

    // ---- prime tile 0 (16 KB image) so it flies during Q/mask prologue ----
    #pragma unroll
    for (int it = 0; it < 4; it++) {
        int idx = tid + it * NTH;                  // 0..1023 chunks of 16B
        cp_async16(sb + SM_KV + idx * 16, kvbase + idx * 16);
    }
    CP_COMMIT();

    // Q scale folds 1/sqrt(Dh)=0.125 and log2(e): exp(s) == exp2(s_scaled)
    const float QSCALE = 0.125f * 1.44269504088896f;

    // ---- prologue: Q (scaled, single fp16) + mask ----
    #pragma unroll 4
    for (int it = 0; it < 16; it++) {
        int idx = tid + it * NTH;
        int m = idx >> 5, dp = idx & 31;
        float2 v = *(const float2*)(Qg + ((size_t)(b * Qv + q0 + m)) * Dm + h * DH + dp * 2);
        __half2 qh = __floats2half2_rn(v.x * QSCALE, v.y * QSCALE);
        *(uint32_t*)(smem + SM_QHI + m * PBB + dp * 4) = *(uint32_t*)&qh;
    }
    for (int s = tid; s < Sv; s += NTH)
        mk[s] = (unsigned char)Mg[(size_t)b * Sv + s];

    // ---- per-thread addresses ----
    // A (Q, pitch-144, unswizzled)
    const uint32_t aAoff = (uint32_t)((wq * 16 + (lane & 15)) * PBB + ((lane & 16) >> 4) * 16);
    const uint32_t aAhi = sb + SM_QHI + aAoff;

    // B (K/V, pitch-128 swizzled images)
    const int s7 = lane & 7;
    const int cb = (lane & 8) >> 3;                 // K col half
    const int vb = (lane >> 4) & 1;                 // V col half
    const uint32_t rowK = (uint32_t)((lane & 7) + ((lane & 16) >> 1)) * 128;
    const uint32_t rowV = (uint32_t)((lane & 7) + (lane & 8)) * 128;
    uint32_t kc[4], vc[4];
    #pragma unroll
    for (int k4 = 0; k4 < 4; k4++) kc[k4] = (uint32_t)((((k4 << 1) | cb) ^ s7) << 4);
    #pragma unroll
    for (int np = 0; np < 4; np++) vc[np] = (uint32_t)((((np << 1) | vb) ^ s7) << 4);

    const int r = lane >> 2, c = lane & 3;

    float O[8][4];
    #pragma unroll
    for (int nt = 0; nt < 8; nt++)
        #pragma unroll
        for (int j = 0; j < 4; j++) O[nt][j] = 0.0f;
    float rsl = 0.0f, rsh = 0.0f;

    // ================= PASS A: rowsums + O (no attn writes) =================
    for (int i = 0; i < NTILES; i++) {
        CP_WAIT0();
        __syncthreads();   // tile i image visible; buf[(i+1)&1] free

        if (i + 1 < NTILES) {
            const unsigned char* g = kvbase + (size_t)(i + 1) * 16384;
            uint32_t dst = sb + SM_KV + ((i + 1) & 1) * 16384;
            #pragma unroll
            for (int it = 0; it < 4; it++) {
                int idx = tid + it * NTH;
                cp_async16(dst + idx * 16, g + idx * 16);
            }
        }
        CP_COMMIT();

        const uint32_t bufK = sb + SM_KV + (i & 1) * 16384;   // K | V(+8192)

        // MMA1 single-pass: S = Q·K (same rounding as pass B -> consistent softmax)
        float S[8][4];
        #pragma unroll
        for (int nt = 0; nt < 8; nt++)
            #pragma unroll
            for (int j = 0; j < 4; j++) S[nt][j] = 0.0f;

        #pragma unroll
        for (int k4 = 0; k4 < 4; k4++) {
            uint32_t ah[4];
            ldm4(ah, aAhi + k4 * 32);
            #pragma unroll
            for (int np = 0; np < 4; np++) {
                uint32_t bo = rowK + np * 2048 + kc[k4];
                uint32_t bk[4];
                ldm4(bk, bufK + bo);
                mma16816(S[2*np],   ah, bk[0], bk[1]);
                mma16816(S[2*np+1], ah, bk[2], bk[3]);
            }
        }

        // mask * exp2 + rowsum (no store)
        const int s0 = i * ST;
        #pragma unroll
        for (int nt = 0; nt < 8; nt++) {
            int col = nt * 8 + 2 * c;
            float m0 = (float)mk[s0 + col], m1 = (float)mk[s0 + col + 1];
            float e0 = m0 * exp2f(S[nt][0]);
            float e1 = m1 * exp2f(S[nt][1]);
            float e2 = m0 * exp2f(S[nt][2]);
            float e3 = m1 * exp2f(S[nt][3]);
            rsl += e0 + e1; rsh += e2 + e3;
            S[nt][0] = e0; S[nt][1] = e1; S[nt][2] = e2; S[nt][3] = e3;
        }

        // MMA2: O += P·V (single-pass)
        const uint32_t bufV = bufK + 8192;
        #pragma unroll
        for (int kt = 0; kt < 4; kt++) {
            uint32_t ph[4];
            __half2 p0 = __floats2half2_rn(S[2*kt][0],   S[2*kt][1]);
            __half2 p1 = __floats2half2_rn(S[2*kt][2],   S[2*kt][3]);
            __half2 p2 = __floats2half2_rn(S[2*kt+1][0], S[2*kt+1][1]);
            __half2 p3 = __floats2half2_rn(S[2*kt+1][2], S[2*kt+1][3]);
            ph[0] = *(uint32_t*)&p0; ph[1] = *(uint32_t*)&p1;
            ph[2] = *(uint32_t*)&p2; ph[3] = *(uint32_t*)&p3;
            #pragma unroll
            for (int np = 0; np < 4; np++) {
                uint32_t bo = rowV + kt * 2048 + vc[np];
                uint32_t v4[4];
                ldm4t(v4, bufV + bo);
                mma16816(O[2*np],   ph, v4[0], v4[1]);
                mma16816(O[2*np+1], ph, v4[2], v4[3]);
            }
        }
    }

    // ---- prime pass B tile 0 (K image only, 8 KB) into buf0 ----
    #pragma unroll
    for (int it = 0; it < 2; it++) {
        int idx = tid + it * NTH;                  // 0..511 chunks
        cp_async16(sb + SM_KV + idx * 16, kvbase + idx * 16);
    }
    CP_COMMIT();

    // ---- rowsum reduce, rinv, normalize O, write out (overlaps tile-0 fetch) ----
    rsl += __shfl_xor_sync(0xffffffffu, rsl, 1);
    rsl += __shfl_xor_sync(0xffffffffu, rsl, 2);
    rsh += __shfl_xor_sync(0xffffffffu, rsh, 1);
    rsh += __shfl_xor_sync(0xffffffffu, rsh, 2);
    const float il = 1.0f / (rsl + 1e-13f);
    const float ih = 1.0f / (rsh + 1e-13f);

    float* orow0 = outg + (size_t)(b * Qv + q0 + wq * 16 + r)     * Dm + h * DH;
    float* orow1 = outg + (size_t)(b * Qv + q0 + wq * 16 + r + 8) * Dm + h * DH;
    #pragma unroll
    for (int nt = 0; nt < 8; nt++) {
        int col = nt * 8 + 2 * c;
        *(float2*)(orow0 + col) = make_float2(O[nt][0] * il, O[nt][1] * il);
        *(float2*)(orow1 + col) = make_float2(O[nt][2] * ih, O[nt][3] * ih);
    }

    // ================= PASS B: recompute scores (1-pass), write normalized attn =================
    float* arow0 = attng + (((size_t)(b * Qv + q0 + wq * 16 + r)) * Hv + h) * Sv;
    float* arow1 = attng + (((size_t)(b * Qv + q0 + wq * 16 + r + 8)) * Hv + h) * Sv;

    for (int i = 0; i < NTILES; i++) {
        CP_WAIT0();
        __syncthreads();   // K image for tile i visible; other buf free

        if (i + 1 < NTILES) {
            const unsigned char* g = kvbase + (size_t)(i + 1) * 16384;
            uint32_t dst = sb + SM_KV + ((i + 1) & 1) * 16384;
            #pragma unroll
            for (int it = 0; it < 2; it++) {
                int idx = tid + it * NTH;
                cp_async16(dst + idx * 16, g + idx * 16);
            }
        }
        CP_COMMIT();

        const uint32_t bufK = sb + SM_KV + (i & 1) * 16384;

        // MMA1 single-pass: S = Q·K (identical rounding to pass A)
        float S[8][4];
        #pragma unroll
        for (int nt = 0; nt < 8; nt++)
            #pragma unroll
            for (int j = 0; j < 4; j++) S[nt][j] = 0.0f;

        #pragma unroll
        for (int k4 = 0; k4 < 4; k4++) {
            uint32_t ah[4];
            ldm4(ah, aAhi + k4 * 32);
            #pragma unroll
            for (int np = 0; np < 4; np++) {
                uint32_t bo = rowK + np * 2048 + kc[k4];
                uint32_t bk[4];
                ldm4(bk, bufK + bo);
                mma16816(S[2*np],   ah, bk[0], bk[1]);
                mma16816(S[2*np+1], ah, bk[2], bk[3]);
            }
        }

        // normalized attn = m * exp2(S) * rinv, direct coalesced write
        const int s0 = i * ST;
        #pragma unroll
        for (int nt = 0; nt < 8; nt++) {
            int col = nt * 8 + 2 * c;
            float m0 = il * (float)mk[s0 + col], m1 = il * (float)mk[s0 + col + 1];
            float n0 = ih * (float)mk[s0 + col], n1 = ih * (float)mk[s0 + col + 1];
            *(float2*)(arow0 + s0 + col) =
                make_float2(m0 * exp2f(S[nt][0]), m1 * exp2f(S[nt][1]));
            *(float2*)(arow1 + s0 + col) =
                make_float2(n0 * exp2f(S[nt][2]), n1 * exp2f(S[nt][3]));
        }
    }
}

// ======================= launch =======================
extern "C" void kernel_launch(void* const* d_in, const int* in_sizes, int n_in,
                              void* d_out, int out_size)
{
    const float* Qg = (const float*)d_in[0];
    const float* Kg = (const float*)d_in[1];
    const float* Vg = (const float*)d_in[2];
    const int*   Mg = (const int*)d_in[3];

    float* outg  = (float*)d_out;                     // [B,Q,D]
    float* attng = outg + (size_t)Bv * Qv * Dm;       // [B,Q,H,S]

    // K0: pre-convert K/V (2^22 threads)
    split_k0<<<(2u << 21) / 256, 256>>>(Kg, Vg);

    // K1: fused attention (two-pass, writes normalized attn directly)
    cudaFuncSetAttribute(attn_k1, cudaFuncAttributeMaxDynamicSharedMemorySize, SMEM_TOTAL);
    dim3 grid(Qv / MT, Hv, Bv);                       // (8,16,8) = 1024 CTAs
    attn_k1<<<grid, NTH, SMEM_TOTAL>>>(Qg, Mg, outg, attng);
}

// round 16
// speedup vs baseline: 2.7495x; 1.0175x over previous
#include <cuda_runtime.h>
#include <cuda_fp16.h>
#include <cstdint>

// ---------------- problem constants ----------------
#define Bv 8
#define Qv 1024
#define Sv 2048
#define Dm 1024
#define Hv 16
#define DH 64
#define MT 128            // q rows per CTA
#define ST 64             // s per tile
#define NTILES (Sv / ST)  // 32
#define NTH 256

// Q tile pitch (fp16 bytes) -- proven conflict-free for A ldmatrix
#define PB  72
#define PBB (PB * 2)      // 144 B per row

// ---------------- KA smem layout (bytes) ----------------
#define SM_QHI   0
#define SM_MASK  (SM_QHI + MT * PBB)      // 18432 (2048 u8)
#define SM_KV    (SM_MASK + 2048)         // 20480: 2 bufs x 16384 (K 8K | V 8K)
#define SMEM_KA  (SM_KV + 2 * 16384)      // 53248

// ---------------- KB smem layout (bytes) ----------------
#define SB_QHI   0
#define SB_MASK  (SB_QHI + MT * PBB)      // 18432
#define SB_K     (SB_MASK + 2048)         // 20480: 2 bufs x 8192 (K only)
#define SMEM_KB  (SB_K + 2 * 8192)        // 36864 -> 3 CTAs/SM (reg-capped 84)

// scratch: [b][h][tile][K|V][64 rows][128 B], XOR-swizzled 16B chunks  (64 MB)
__device__ __align__(16) unsigned char g_kv[(size_t)Bv * Hv * NTILES * 2 * ST * 128];
__device__ float g_rinv[Bv * Qv * Hv];

// ---------------- helpers ----------------
__device__ __forceinline__ uint32_t su32(const void* p) {
    uint32_t a;
    asm("{ .reg .u64 t; cvta.to.shared.u64 t, %1; cvt.u32.u64 %0, t; }" : "=r"(a) : "l"(p));
    return a;
}

__device__ __forceinline__ void cp_async16(uint32_t dst, const void* src) {
    asm volatile("cp.async.cg.shared.global [%0], [%1], 16;" :: "r"(dst), "l"(src));
}
#define CP_COMMIT() asm volatile("cp.async.commit_group;" ::: "memory")
#define CP_WAIT0()  asm volatile("cp.async.wait_group 0;" ::: "memory")

__device__ __forceinline__ void ldm4(uint32_t* r, uint32_t a) {
    asm volatile("ldmatrix.sync.aligned.m8n8.x4.shared.b16 {%0,%1,%2,%3}, [%4];"
        : "=r"(r[0]), "=r"(r[1]), "=r"(r[2]), "=r"(r[3]) : "r"(a));
}
__device__ __forceinline__ void ldm4t(uint32_t* r, uint32_t a) {
    asm volatile("ldmatrix.sync.aligned.m8n8.x4.trans.shared.b16 {%0,%1,%2,%3}, [%4];"
        : "=r"(r[0]), "=r"(r[1]), "=r"(r[2]), "=r"(r[3]) : "r"(a));
}
__device__ __forceinline__ void mma16816(float* d, const uint32_t* a, uint32_t b0, uint32_t b1) {
    asm volatile("mma.sync.aligned.m16n8k16.row.col.f32.f16.f16.f32 "
        "{%0,%1,%2,%3}, {%4,%5,%6,%7}, {%8,%9}, {%0,%1,%2,%3};"
        : "+f"(d[0]), "+f"(d[1]), "+f"(d[2]), "+f"(d[3])
        : "r"(a[0]), "r"(a[1]), "r"(a[2]), "r"(a[3]), "r"(b0), "r"(b1));
}

#define QSCALE (0.125f * 1.44269504088896f)

// ======================= K0: pre-convert K/V to fp16 swizzled tile images =======================
__global__ void __launch_bounds__(256)
split_k0(const float* __restrict__ Kg, const float* __restrict__ Vg)
{
    int gid = blockIdx.x * 256 + threadIdx.x;
    int c  = gid & 7;
    int s  = (gid >> 3) & 2047;
    int h  = (gid >> 14) & 15;
    int bb = (gid >> 18) & 7;
    int kv = gid >> 21;

    const float* src = (kv ? Vg : Kg) + ((size_t)bb * Sv + s) * Dm + h * DH + c * 8;
    float4 f0 = *(const float4*)src;
    float4 f1 = *(const float4*)(src + 4);
    __half2 h0 = __floats2half2_rn(f0.x, f0.y);
    __half2 h1 = __floats2half2_rn(f0.z, f0.w);
    __half2 h2 = __floats2half2_rn(f1.x, f1.y);
    __half2 h3 = __floats2half2_rn(f1.z, f1.w);

    int tile = s >> 6, row = s & 63;
    int cph  = c ^ (row & 7);                       // XOR swizzle
    size_t base = (((size_t)(bb * Hv + h) * NTILES + tile) * 2 + kv) * 8192
                + row * 128 + cph * 16;
    *(uint4*)(g_kv + base) = make_uint4(*(uint32_t*)&h0, *(uint32_t*)&h1,
                                        *(uint32_t*)&h2, *(uint32_t*)&h3);
}

// ======================= KA: pass A — rowsums + O + rinv =======================
extern __shared__ char smem[];

__global__ void __launch_bounds__(NTH, 2)
attn_ka(const float* __restrict__ Qg, const int* __restrict__ Mg,
        float* __restrict__ outg)
{
    const int tid  = threadIdx.x;
    const int lane = tid & 31;
    const int wq   = tid >> 5;
    const int q0   = blockIdx.x * MT;
    const int h    = blockIdx.y;
    const int b    = blockIdx.z;

    const uint32_t sb = su32(smem);
    unsigned char* mk = (unsigned char*)(smem + SM_MASK);

    const unsigned char* kvbase = g_kv + (size_t)(b * Hv + h) * NTILES * 16384;

    // prime tile 0 (16 KB: K | V)
    #pragma unroll
    for (int it = 0; it < 4; it++) {
        int idx = tid + it * NTH;
        cp_async16(sb + SM_KV + idx * 16, kvbase + idx * 16);
    }
    CP_COMMIT();

    // prologue: Q (scaled, single fp16) + mask
    #pragma unroll 4
    for (int it = 0; it < 16; it++) {
        int idx = tid + it * NTH;
        int m = idx >> 5, dp = idx & 31;
        float2 v = *(const float2*)(Qg + ((size_t)(b * Qv + q0 + m)) * Dm + h * DH + dp * 2);
        __half2 qh = __floats2half2_rn(v.x * QSCALE, v.y * QSCALE);
        *(uint32_t*)(smem + SM_QHI + m * PBB + dp * 4) = *(uint32_t*)&qh;
    }
    for (int s = tid; s < Sv; s += NTH)
        mk[s] = (unsigned char)Mg[(size_t)b * Sv + s];

    // per-thread addresses
    const uint32_t aAoff = (uint32_t)((wq * 16 + (lane & 15)) * PBB + ((lane & 16) >> 4) * 16);
    const uint32_t aAhi = sb + SM_QHI + aAoff;
    const int s7 = lane & 7;
    const int cb = (lane & 8) >> 3;
    const int vb = (lane >> 4) & 1;
    const uint32_t rowK = (uint32_t)((lane & 7) + ((lane & 16) >> 1)) * 128;
    const uint32_t rowV = (uint32_t)((lane & 7) + (lane & 8)) * 128;
    uint32_t kc[4], vc[4];
    #pragma unroll
    for (int k4 = 0; k4 < 4; k4++) kc[k4] = (uint32_t)((((k4 << 1) | cb) ^ s7) << 4);
    #pragma unroll
    for (int np = 0; np < 4; np++) vc[np] = (uint32_t)((((np << 1) | vb) ^ s7) << 4);

    const int r = lane >> 2, c = lane & 3;

    float O[8][4];
    #pragma unroll
    for (int nt = 0; nt < 8; nt++)
        #pragma unroll
        for (int j = 0; j < 4; j++) O[nt][j] = 0.0f;
    float rsl = 0.0f, rsh = 0.0f;

    for (int i = 0; i < NTILES; i++) {
        CP_WAIT0();
        __syncthreads();

        if (i + 1 < NTILES) {
            const unsigned char* g = kvbase + (size_t)(i + 1) * 16384;
            uint32_t dst = sb + SM_KV + ((i + 1) & 1) * 16384;
            #pragma unroll
            for (int it = 0; it < 4; it++) {
                int idx = tid + it * NTH;
                cp_async16(dst + idx * 16, g + idx * 16);
            }
        }
        CP_COMMIT();

        const uint32_t bufK = sb + SM_KV + (i & 1) * 16384;

        // MMA1 single-pass: S = Q·K
        float S[8][4];
        #pragma unroll
        for (int nt = 0; nt < 8; nt++)
            #pragma unroll
            for (int j = 0; j < 4; j++) S[nt][j] = 0.0f;

        #pragma unroll
        for (int k4 = 0; k4 < 4; k4++) {
            uint32_t ah[4];
            ldm4(ah, aAhi + k4 * 32);
            #pragma unroll
            for (int np = 0; np < 4; np++) {
                uint32_t bo = rowK + np * 2048 + kc[k4];
                uint32_t bk[4];
                ldm4(bk, bufK + bo);
                mma16816(S[2*np],   ah, bk[0], bk[1]);
                mma16816(S[2*np+1], ah, bk[2], bk[3]);
            }
        }

        // mask * exp2 + rowsum
        const int s0 = i * ST;
        #pragma unroll
        for (int nt = 0; nt < 8; nt++) {
            int col = nt * 8 + 2 * c;
            float m0 = (float)mk[s0 + col], m1 = (float)mk[s0 + col + 1];
            float e0 = m0 * exp2f(S[nt][0]);
            float e1 = m1 * exp2f(S[nt][1]);
            float e2 = m0 * exp2f(S[nt][2]);
            float e3 = m1 * exp2f(S[nt][3]);
            rsl += e0 + e1; rsh += e2 + e3;
            S[nt][0] = e0; S[nt][1] = e1; S[nt][2] = e2; S[nt][3] = e3;
        }

        // MMA2: O += P·V
        const uint32_t bufV = bufK + 8192;
        #pragma unroll
        for (int kt = 0; kt < 4; kt++) {
            uint32_t ph[4];
            __half2 p0 = __floats2half2_rn(S[2*kt][0],   S[2*kt][1]);
            __half2 p1 = __floats2half2_rn(S[2*kt][2],   S[2*kt][3]);
            __half2 p2 = __floats2half2_rn(S[2*kt+1][0], S[2*kt+1][1]);
            __half2 p3 = __floats2half2_rn(S[2*kt+1][2], S[2*kt+1][3]);
            ph[0] = *(uint32_t*)&p0; ph[1] = *(uint32_t*)&p1;
            ph[2] = *(uint32_t*)&p2; ph[3] = *(uint32_t*)&p3;
            #pragma unroll
            for (int np = 0; np < 4; np++) {
                uint32_t bo = rowV + kt * 2048 + vc[np];
                uint32_t v4[4];
                ldm4t(v4, bufV + bo);
                mma16816(O[2*np],   ph, v4[0], v4[1]);
                mma16816(O[2*np+1], ph, v4[2], v4[3]);
            }
        }
    }

    // rowsum reduce, rinv, normalize O, write out + rinv
    rsl += __shfl_xor_sync(0xffffffffu, rsl, 1);
    rsl += __shfl_xor_sync(0xffffffffu, rsl, 2);
    rsh += __shfl_xor_sync(0xffffffffu, rsh, 1);
    rsh += __shfl_xor_sync(0xffffffffu, rsh, 2);
    const float il = 1.0f / (rsl + 1e-13f);
    const float ih = 1.0f / (rsh + 1e-13f);

    if (c == 0) {
        g_rinv[(size_t)(b * Qv + q0 + wq * 16 + r)     * Hv + h] = il;
        g_rinv[(size_t)(b * Qv + q0 + wq * 16 + r + 8) * Hv + h] = ih;
    }

    float* orow0 = outg + (size_t)(b * Qv + q0 + wq * 16 + r)     * Dm + h * DH;
    float* orow1 = outg + (size_t)(b * Qv + q0 + wq * 16 + r + 8) * Dm + h * DH;
    #pragma unroll
    for (int nt = 0; nt < 8; nt++) {
        int col = nt * 8 + 2 * c;
        *(float2*)(orow0 + col) = make_float2(O[nt][0] * il, O[nt][1] * il);
        *(float2*)(orow1 + col) = make_float2(O[nt][2] * ih, O[nt][3] * ih);
    }
}

// ======================= KB: pass B — recompute scores, write normalized attn =======================
// Low-register kernel: 3 CTAs/SM (launch_bounds caps regs at 84)
__global__ void __launch_bounds__(NTH, 3)
attn_kb(const float* __restrict__ Qg, const int* __restrict__ Mg,
        float* __restrict__ attng)
{
    const int tid  = threadIdx.x;
    const int lane = tid & 31;
    const int wq   = tid >> 5;
    const int q0   = blockIdx.x * MT;
    const int h    = blockIdx.y;
    const int b    = blockIdx.z;

    const uint32_t sb = su32(smem);
    unsigned char* mk = (unsigned char*)(smem + SB_MASK);

    const unsigned char* kvbase = g_kv + (size_t)(b * Hv + h) * NTILES * 16384;

    // prime tile 0 K image (8 KB)
    #pragma unroll
    for (int it = 0; it < 2; it++) {
        int idx = tid + it * NTH;
        cp_async16(sb + SB_K + idx * 16, kvbase + idx * 16);
    }
    CP_COMMIT();

    // prologue: Q (scaled fp16) + mask
    #pragma unroll 4
    for (int it = 0; it < 16; it++) {
        int idx = tid + it * NTH;
        int m = idx >> 5, dp = idx & 31;
        float2 v = *(const float2*)(Qg + ((size_t)(b * Qv + q0 + m)) * Dm + h * DH + dp * 2);
        __half2 qh = __floats2half2_rn(v.x * QSCALE, v.y * QSCALE);
        *(uint32_t*)(smem + SB_QHI + m * PBB + dp * 4) = *(uint32_t*)&qh;
    }
    for (int s = tid; s < Sv; s += NTH)
        mk[s] = (unsigned char)Mg[(size_t)b * Sv + s];

    // per-thread addresses
    const uint32_t aAoff = (uint32_t)((wq * 16 + (lane & 15)) * PBB + ((lane & 16) >> 4) * 16);
    const uint32_t aAhi = sb + SB_QHI + aAoff;
    const int s7 = lane & 7;
    const int cb = (lane & 8) >> 3;
    const uint32_t rowK = (uint32_t)((lane & 7) + ((lane & 16) >> 1)) * 128;
    uint32_t kc[4];
    #pragma unroll
    for (int k4 = 0; k4 < 4; k4++) kc[k4] = (uint32_t)((((k4 << 1) | cb) ^ s7) << 4);

    const int r = lane >> 2, c = lane & 3;

    // rinv for this thread's two rows; fold into exp2 exponent
    const float il = g_rinv[(size_t)(b * Qv + q0 + wq * 16 + r)     * Hv + h];
    const float ih = g_rinv[(size_t)(b * Qv + q0 + wq * 16 + r + 8) * Hv + h];
    const float lgl = __log2f(il);
    const float lgh = __log2f(ih);

    float* arow0 = attng + (((size_t)(b * Qv + q0 + wq * 16 + r)) * Hv + h) * Sv;
    float* arow1 = attng + (((size_t)(b * Qv + q0 + wq * 16 + r + 8)) * Hv + h) * Sv;

    for (int i = 0; i < NTILES; i++) {
        CP_WAIT0();
        __syncthreads();

        if (i + 1 < NTILES) {
            const unsigned char* g = kvbase + (size_t)(i + 1) * 16384;
            uint32_t dst = sb + SB_K + ((i + 1) & 1) * 8192;
            #pragma unroll
            for (int it = 0; it < 2; it++) {
                int idx = tid + it * NTH;
                cp_async16(dst + idx * 16, g + idx * 16);
            }
        }
        CP_COMMIT();

        const uint32_t bufK = sb + SB_K + (i & 1) * 8192;

        // MMA1 single-pass: S = Q·K (identical rounding to KA)
        float S[8][4];
        #pragma unroll
        for (int nt = 0; nt < 8; nt++)
            #pragma unroll
            for (int j = 0; j < 4; j++) S[nt][j] = 0.0f;

        #pragma unroll
        for (int k4 = 0; k4 < 4; k4++) {
            uint32_t ah[4];
            ldm4(ah, aAhi + k4 * 32);
            #pragma unroll
            for (int np = 0; np < 4; np++) {
                uint32_t bo = rowK + np * 2048 + kc[k4];
                uint32_t bk[4];
                ldm4(bk, bufK + bo);
                mma16816(S[2*np],   ah, bk[0], bk[1]);
                mma16816(S[2*np+1], ah, bk[2], bk[3]);
            }
        }

        // attn = m * exp2(S + lg(rinv)), direct coalesced write
        const int s0 = i * ST;
        #pragma unroll
        for (int nt = 0; nt < 8; nt++) {
            int col = nt * 8 + 2 * c;
            float m0 = (float)mk[s0 + col], m1 = (float)mk[s0 + col + 1];
            *(float2*)(arow0 + s0 + col) =
                make_float2(m0 * exp2f(S[nt][0] + lgl), m1 * exp2f(S[nt][1] + lgl));
            *(float2*)(arow1 + s0 + col) =
                make_float2(m0 * exp2f(S[nt][2] + lgh), m1 * exp2f(S[nt][3] + lgh));
        }
    }
}

// ======================= launch =======================
extern "C" void kernel_launch(void* const* d_in, const int* in_sizes, int n_in,
                              void* d_out, int out_size)
{
    const float* Qg = (const float*)d_in[0];
    const float* Kg = (const float*)d_in[1];
    const float* Vg = (const float*)d_in[2];
    const int*   Mg = (const int*)d_in[3];

    float* outg  = (float*)d_out;                     // [B,Q,D]
    float* attng = outg + (size_t)Bv * Qv * Dm;       // [B,Q,H,S]

    // K0: pre-convert K/V (2^22 threads)
    split_k0<<<(2u << 21) / 256, 256>>>(Kg, Vg);

    dim3 grid(Qv / MT, Hv, Bv);                       // (8,16,8) = 1024 CTAs

    // KA: pass A (out + rinv)
    cudaFuncSetAttribute(attn_ka, cudaFuncAttributeMaxDynamicSharedMemorySize, SMEM_KA);
    attn_ka<<<grid, NTH, SMEM_KA>>>(Qg, Mg, outg);

    // KB: pass B (normalized attn), 3 CTAs/SM
    cudaFuncSetAttribute(attn_kb, cudaFuncAttributeMaxDynamicSharedMemorySize, SMEM_KB);
    attn_kb<<<grid, NTH, SMEM_KB>>>(Qg, Mg, attng);
}